// round 4
// baseline (speedup 1.0000x reference)
#include <cuda_runtime.h>
#include <math.h>
#include <stdint.h>

#define Bdim 2
#define Sdim 2048
#define Edim 1024
#define Hdim 16
#define HDdim 64
#define RDdim 32
#define LOCAL 128          // HD*H/MP
#define MROWS (Bdim*Sdim)  // 4096
#define FULLMASK 0xffffffffu

// Scratch (allocation-free per harness rules)
__device__ float g_qkv[Bdim*Sdim*3*Edim];
__device__ float g_q[Bdim*Hdim*Sdim*HDdim];   // tf32-pre-rounded
__device__ float g_k[Bdim*Hdim*Sdim*HDdim];   // tf32-pre-rounded
__device__ float g_v[Bdim*Hdim*Sdim*HDdim];   // tf32-pre-rounded
__device__ float g_ctx[Bdim*Sdim*Edim];       // [b,s,h,d]

__device__ __forceinline__ float to_tf32(float x) {
    uint32_t u;
    asm("cvt.rna.tf32.f32 %0, %1;" : "=r"(u) : "f"(x));
    return __uint_as_float(u);
}
__device__ __forceinline__ uint32_t f2u(float x) { return __float_as_uint(x); }
__device__ __forceinline__ uint32_t lds_tf32(const float* p) {
    uint32_t u;
    asm("cvt.rna.tf32.f32 %0, %1;" : "=r"(u) : "f"(*p));
    return u;
}
__device__ __forceinline__ uint32_t smaddr(const void* p) {
    return (uint32_t)__cvta_generic_to_shared(p);
}
__device__ __forceinline__ void cp_async16(uint32_t dst, const void* src) {
    asm volatile("cp.async.cg.shared.global [%0], [%1], 16;" :: "r"(dst), "l"(src));
}
__device__ __forceinline__ void cp_commit() {
    asm volatile("cp.async.commit_group;");
}
template<int N> __device__ __forceinline__ void cp_wait() {
    asm volatile("cp.async.wait_group %0;" :: "n"(N));
}

__device__ __forceinline__ void mma_tf32(float c[4],
    uint32_t a0, uint32_t a1, uint32_t a2, uint32_t a3,
    uint32_t b0, uint32_t b1)
{
    asm volatile(
        "mma.sync.aligned.m16n8k8.row.col.f32.tf32.tf32.f32 "
        "{%0,%1,%2,%3}, {%4,%5,%6,%7}, {%8,%9}, {%0,%1,%2,%3};"
        : "+f"(c[0]), "+f"(c[1]), "+f"(c[2]), "+f"(c[3])
        : "r"(a0), "r"(a1), "r"(a2), "r"(a3), "r"(b0), "r"(b1));
}

// ---------------------------------------------------------------------------
// TF32 GEMM with 2-stage cp.async pipeline: C[M,N] = A[M,K] @ W[N,K]^T
// BM=128, BN=128, BK=32, 256 threads (8 warps 4x2), warp tile 32x64.
// tf32 conversion at fragment load (smem holds raw fp32 from cp.async).
// ---------------------------------------------------------------------------
#define AST 36
__global__ __launch_bounds__(256) void sgemm_tf32(
    const float* __restrict__ A, const float* __restrict__ W,
    float* __restrict__ C, int M, int N, int K)
{
    extern __shared__ float sm[];    // [stage][A(128*AST) | W(128*AST)]
    const int tid  = threadIdx.x;
    const int lane = tid & 31, wid = tid >> 5;
    const int gid  = lane >> 2, tig = lane & 3;
    const int wm   = (wid & 3) * 32;
    const int wn   = (wid >> 2) * 64;
    const int m0   = blockIdx.y * 128;
    const int n0   = blockIdx.x * 128;

    auto issue = [&](int st, int k0) {
        float* As = sm + st * (2 * 128 * AST);
        float* Ws = As + 128 * AST;
#pragma unroll
        for (int it = 0; it < 4; it++) {
            int idx = tid + it * 256;
            int r = idx >> 3, c4 = idx & 7;
            cp_async16(smaddr(As + r * AST + c4 * 4), A + (size_t)(m0 + r) * K + k0 + c4 * 4);
            cp_async16(smaddr(Ws + r * AST + c4 * 4), W + (size_t)(n0 + r) * K + k0 + c4 * 4);
        }
        cp_commit();
    };

    float c[2][8][4];
#pragma unroll
    for (int mi = 0; mi < 2; mi++)
#pragma unroll
        for (int ni = 0; ni < 8; ni++)
#pragma unroll
            for (int j = 0; j < 4; j++) c[mi][ni][j] = 0.0f;

    const int nt = K / 32;
    issue(0, 0);
    for (int t = 0; t < nt; t++) {
        if (t + 1 < nt) { issue((t + 1) & 1, (t + 1) * 32); cp_wait<1>(); }
        else            { cp_wait<0>(); }
        __syncthreads();
        const float* As = sm + (t & 1) * (2 * 128 * AST);
        const float* Ws = As + 128 * AST;

#pragma unroll
        for (int kk = 0; kk < 4; kk++) {
            const int kb = kk * 8;
            uint32_t a[2][4];
#pragma unroll
            for (int mi = 0; mi < 2; mi++) {
                int rb = wm + mi * 16;
                a[mi][0] = lds_tf32(As + (rb + gid    ) * AST + kb + tig    );
                a[mi][1] = lds_tf32(As + (rb + gid + 8) * AST + kb + tig    );
                a[mi][2] = lds_tf32(As + (rb + gid    ) * AST + kb + tig + 4);
                a[mi][3] = lds_tf32(As + (rb + gid + 8) * AST + kb + tig + 4);
            }
#pragma unroll
            for (int ni = 0; ni < 8; ni++) {
                uint32_t b0 = lds_tf32(Ws + (wn + ni * 8 + gid) * AST + kb + tig    );
                uint32_t b1 = lds_tf32(Ws + (wn + ni * 8 + gid) * AST + kb + tig + 4);
                mma_tf32(c[0][ni], a[0][0], a[0][1], a[0][2], a[0][3], b0, b1);
                mma_tf32(c[1][ni], a[1][0], a[1][1], a[1][2], a[1][3], b0, b1);
            }
        }
        __syncthreads();
    }

#pragma unroll
    for (int mi = 0; mi < 2; mi++) {
#pragma unroll
        for (int ni = 0; ni < 8; ni++) {
            int r  = m0 + wm + mi * 16 + gid;
            int cc = n0 + wn + ni * 8 + 2 * tig;
            float2 v01 = make_float2(c[mi][ni][0], c[mi][ni][1]);
            float2 v23 = make_float2(c[mi][ni][2], c[mi][ni][3]);
            *(float2*)(C + (size_t)r * N + cc)       = v01;
            *(float2*)(C + (size_t)(r + 8) * N + cc) = v23;
        }
    }
}

// ---------------------------------------------------------------------------
// QKV de-interleave + RoPE (reference split order q, v, k).
// Outputs pre-rounded to tf32 so flash can copy raw bytes.
// ---------------------------------------------------------------------------
__global__ __launch_bounds__(256) void qkv_transform(const float* __restrict__ qkv)
{
    int idx = blockIdx.x * blockDim.x + threadIdx.x;
    if (idx >= Bdim * Sdim * Hdim * HDdim) return;
    int d = idx & (HDdim - 1);
    int h = (idx >> 6) & (Hdim - 1);
    int s = (idx >> 10) & (Sdim - 1);
    int b = idx >> 21;

    int mp = h >> 1, r = h & 1;
    const float* base = qkv + (size_t)(b * Sdim + s) * (3 * Edim) + mp * (3 * LOCAL) + r * HDdim;

    float qv = base[d];
    float vv = base[LOCAL + d];
    float kv = base[2 * LOCAL + d];

    if (d < RDdim) {
        int i = d >> 1;
        // 10000^(-2i/RD) = exp(-i * ln(10000)/16)
        float inv = expf(-(float)i * 0.5756462732485115f);
        float ang = (float)s * inv;
        float sn, cs;
        sincosf(ang, &sn, &cs);
        int partner = d ^ 1;
        float qp = base[partner];
        float kp = base[2 * LOCAL + partner];
        if ((d & 1) == 0) {
            qv = qv * cs - qp * sn;
            kv = kv * cs - kp * sn;
        } else {
            qv = qv * cs + qp * sn;
            kv = kv * cs + kp * sn;
        }
    }
    size_t o = (size_t)((b * Hdim + h) * Sdim + s) * HDdim + d;
    g_q[o] = to_tf32(qv);
    g_k[o] = to_tf32(kv);
    g_v[o] = to_tf32(vv);
}

// ---------------------------------------------------------------------------
// Flash attention: 128-query tiles, 8 warps (16 rows each), 64-key tiles,
// 2-stage cp.async K/V double buffer, shuffle-transpose P (no smem P).
// smem = 2 stages x (Ks 64x68 + Vs 64x68) = 69632 B dynamic.
// ---------------------------------------------------------------------------
#define KST 68
#define TILE_F (64 * KST)
__global__ void __launch_bounds__(256, 2) flash_mma()
{
    extern __shared__ float fsm[];
    const int qt  = 15 - (int)blockIdx.x;   // heavy tiles first
    const int bh  = blockIdx.y;
    const int tid = threadIdx.x;
    const int lane = tid & 31, w = tid >> 5;
    const int gid = lane >> 2, tig = lane & 3;

    const float* Kh = g_k + (size_t)bh * Sdim * HDdim;
    const float* Vh = g_v + (size_t)bh * Sdim * HDdim;

    auto issueKV = [&](int kt, int st) {
        const float* Kb = Kh + (size_t)kt * 64 * HDdim;
        const float* Vb = Vh + (size_t)kt * 64 * HDdim;
        float* Ks = fsm + st * (2 * TILE_F);
        float* Vs = Ks + TILE_F;
#pragma unroll
        for (int it = 0; it < 4; it++) {
            int idx = tid + it * 256;          // 0..1023
            int r = idx >> 4, c4 = idx & 15;
            cp_async16(smaddr(Ks + r * KST + c4 * 4), Kb + (size_t)r * HDdim + c4 * 4);
            cp_async16(smaddr(Vs + r * KST + c4 * 4), Vb + (size_t)r * HDdim + c4 * 4);
        }
        cp_commit();
    };

    const int nk = 2 * qt + 2;
    issueKV(0, 0);

    // Q fragments straight from gmem (values already tf32-rounded)
    const float* Qb = g_q + ((size_t)bh * Sdim + qt * 128 + w * 16) * HDdim;
    uint32_t qa[8][4];
#pragma unroll
    for (int kk = 0; kk < 8; kk++) {
        qa[kk][0] = f2u(Qb[(size_t)(gid    ) * HDdim + kk * 8 + tig    ]);
        qa[kk][1] = f2u(Qb[(size_t)(gid + 8) * HDdim + kk * 8 + tig    ]);
        qa[kk][2] = f2u(Qb[(size_t)(gid    ) * HDdim + kk * 8 + tig + 4]);
        qa[kk][3] = f2u(Qb[(size_t)(gid + 8) * HDdim + kk * 8 + tig + 4]);
    }

    float m0r = -1e30f, m1r = -1e30f, l0 = 0.0f, l1 = 0.0f;
    float o[8][4];
#pragma unroll
    for (int ni = 0; ni < 8; ni++)
#pragma unroll
        for (int j = 0; j < 4; j++) o[ni][j] = 0.0f;

    const float scale = 0.125f;                 // 1/sqrt(64)
    const int row0 = qt * 128 + w * 16 + gid;   // thread's row (and row0+8)

    for (int kt = 0; kt < nk; kt++) {
        if (kt + 1 < nk) { issueKV(kt + 1, (kt + 1) & 1); cp_wait<1>(); }
        else             { cp_wait<0>(); }
        __syncthreads();
        const float* Ks = fsm + (kt & 1) * (2 * TILE_F);
        const float* Vs = Ks + TILE_F;

        // S = Q @ K^T
        float s[8][4];
#pragma unroll
        for (int ni = 0; ni < 8; ni++)
#pragma unroll
            for (int j = 0; j < 4; j++) s[ni][j] = 0.0f;
#pragma unroll
        for (int kk = 0; kk < 8; kk++) {
            int kb = kk * 8;
#pragma unroll
            for (int ni = 0; ni < 8; ni++) {
                uint32_t b0 = f2u(Ks[(ni * 8 + gid) * KST + kb + tig    ]);
                uint32_t b1 = f2u(Ks[(ni * 8 + gid) * KST + kb + tig + 4]);
                mma_tf32(s[ni], qa[kk][0], qa[kk][1], qa[kk][2], qa[kk][3], b0, b1);
            }
        }

        // scale + causal mask (only last two tiles can be partial)
        if (kt >= 2 * qt) {
#pragma unroll
            for (int ni = 0; ni < 8; ni++)
#pragma unroll
                for (int j = 0; j < 4; j++) {
                    int col  = kt * 64 + ni * 8 + 2 * tig + (j & 1);
                    int rowg = row0 + ((j >= 2) ? 8 : 0);
                    s[ni][j] = (col > rowg) ? -1e9f : s[ni][j] * scale;
                }
        } else {
#pragma unroll
            for (int ni = 0; ni < 8; ni++)
#pragma unroll
                for (int j = 0; j < 4; j++) s[ni][j] *= scale;
        }

        // online softmax (rows gid, gid+8)
        float mx0 = -1e30f, mx1 = -1e30f;
#pragma unroll
        for (int ni = 0; ni < 8; ni++) {
            mx0 = fmaxf(mx0, fmaxf(s[ni][0], s[ni][1]));
            mx1 = fmaxf(mx1, fmaxf(s[ni][2], s[ni][3]));
        }
        mx0 = fmaxf(mx0, __shfl_xor_sync(FULLMASK, mx0, 1));
        mx0 = fmaxf(mx0, __shfl_xor_sync(FULLMASK, mx0, 2));
        mx1 = fmaxf(mx1, __shfl_xor_sync(FULLMASK, mx1, 1));
        mx1 = fmaxf(mx1, __shfl_xor_sync(FULLMASK, mx1, 2));

        float mn0 = fmaxf(m0r, mx0), mn1 = fmaxf(m1r, mx1);
        float al0 = __expf(m0r - mn0), al1 = __expf(m1r - mn1);
        float rs0 = 0.0f, rs1 = 0.0f;
#pragma unroll
        for (int ni = 0; ni < 8; ni++) {
            float p0 = __expf(s[ni][0] - mn0); s[ni][0] = p0; rs0 += p0;
            float p1 = __expf(s[ni][1] - mn0); s[ni][1] = p1; rs0 += p1;
            float p2 = __expf(s[ni][2] - mn1); s[ni][2] = p2; rs1 += p2;
            float p3 = __expf(s[ni][3] - mn1); s[ni][3] = p3; rs1 += p3;
        }
        rs0 += __shfl_xor_sync(FULLMASK, rs0, 1);
        rs0 += __shfl_xor_sync(FULLMASK, rs0, 2);
        rs1 += __shfl_xor_sync(FULLMASK, rs1, 1);
        rs1 += __shfl_xor_sync(FULLMASK, rs1, 2);

        l0 = l0 * al0 + rs0;  l1 = l1 * al1 + rs1;
        m0r = mn0;  m1r = mn1;
#pragma unroll
        for (int ni = 0; ni < 8; ni++) {
            o[ni][0] *= al0; o[ni][1] *= al0;
            o[ni][2] *= al1; o[ni][3] *= al1;
        }

        // O += P @ V : C-frag -> A-frag via register shuffles
        const int src0 = (lane & 28) | (tig >> 1);   // gid*4 + tig/2
        const int src1 = src0 + 2;
        const bool odd = (tig & 1);
#pragma unroll
        for (int kk = 0; kk < 8; kk++) {
            float v00 = __shfl_sync(FULLMASK, s[kk][0], src0);
            float v01 = __shfl_sync(FULLMASK, s[kk][1], src0);
            float v10 = __shfl_sync(FULLMASK, s[kk][2], src0);
            float v11 = __shfl_sync(FULLMASK, s[kk][3], src0);
            float u00 = __shfl_sync(FULLMASK, s[kk][0], src1);
            float u01 = __shfl_sync(FULLMASK, s[kk][1], src1);
            float u10 = __shfl_sync(FULLMASK, s[kk][2], src1);
            float u11 = __shfl_sync(FULLMASK, s[kk][3], src1);
            uint32_t pa0 = f2u(to_tf32(odd ? v01 : v00));
            uint32_t pa1 = f2u(to_tf32(odd ? v11 : v10));
            uint32_t pa2 = f2u(to_tf32(odd ? u01 : u00));
            uint32_t pa3 = f2u(to_tf32(odd ? u11 : u10));
            int kb = kk * 8;
#pragma unroll
            for (int ni = 0; ni < 8; ni++) {
                uint32_t b0 = f2u(Vs[(kb + tig    ) * KST + ni * 8 + gid]);
                uint32_t b1 = f2u(Vs[(kb + tig + 4) * KST + ni * 8 + gid]);
                mma_tf32(o[ni], pa0, pa1, pa2, pa3, b0, b1);
            }
        }
        __syncthreads();
    }

    // epilogue -> g_ctx[b, s, h, d]
    const int b = bh >> 4, h = bh & 15;
    const float inv0 = 1.0f / l0, inv1 = 1.0f / l1;
#pragma unroll
    for (int ni = 0; ni < 8; ni++) {
        int d0 = ni * 8 + 2 * tig;
        float2 v01 = make_float2(o[ni][0] * inv0, o[ni][1] * inv0);
        float2 v23 = make_float2(o[ni][2] * inv1, o[ni][3] * inv1);
        *(float2*)(g_ctx + (size_t)((b * Sdim + row0    ) * Hdim + h) * HDdim + d0) = v01;
        *(float2*)(g_ctx + (size_t)((b * Sdim + row0 + 8) * Hdim + h) * HDdim + d0) = v23;
    }
}

// ---------------------------------------------------------------------------
extern "C" void kernel_launch(void* const* d_in, const int* in_sizes, int n_in,
                              void* d_out, int out_size)
{
    const float* hs    = (const float*)d_in[0];   // [B,S,E]
    const float* w_qkv = (const float*)d_in[1];   // [3E,E]
    const float* w_out = (const float*)d_in[2];   // [E,E]
    float* out = (float*)d_out;                   // [B,S,E]

    float *p_qkv, *p_ctx;
    cudaGetSymbolAddress((void**)&p_qkv, g_qkv);
    cudaGetSymbolAddress((void**)&p_ctx, g_ctx);

    const int GS = 4 * 128 * AST * sizeof(float);   // 73728 B (2 stages A+W)
    const int FS = 4 * TILE_F * sizeof(float);      // 69632 B (2 stages K+V)
    static bool attr_done = false;
    if (!attr_done) {
        cudaFuncSetAttribute(sgemm_tf32, cudaFuncAttributeMaxDynamicSharedMemorySize, GS);
        cudaFuncSetAttribute(flash_mma,  cudaFuncAttributeMaxDynamicSharedMemorySize, FS);
        attr_done = true;
    }

    // 1) QKV projection: [4096,1024] @ [3072,1024]^T
    {
        dim3 grid(3 * Edim / 128, MROWS / 128);
        sgemm_tf32<<<grid, 256, GS>>>(hs, w_qkv, p_qkv, MROWS, 3 * Edim, Edim);
    }
    // 2) split + RoPE (tf32 pre-round)
    {
        int total = Bdim * Sdim * Hdim * HDdim;
        qkv_transform<<<(total + 255) / 256, 256>>>(p_qkv);
    }
    // 3) flash attention (128-query tiles, cp.async double buffer)
    {
        dim3 grid(Sdim / 128, Bdim * Hdim);
        flash_mma<<<grid, 256, FS>>>();
    }
    // 4) output projection: [4096,1024] @ [1024,1024]^T
    {
        dim3 grid(Edim / 128, MROWS / 128);
        sgemm_tf32<<<grid, 256, GS>>>(p_ctx, w_out, out, MROWS, Edim, Edim);
    }
}

// round 7
// speedup vs baseline: 1.0892x; 1.0892x over previous
#include <cuda_runtime.h>
#include <math.h>
#include <stdint.h>

#define Bdim 2
#define Sdim 2048
#define Edim 1024
#define Hdim 16
#define HDdim 64
#define RDdim 32
#define LOCAL 128          // HD*H/MP
#define MROWS (Bdim*Sdim)  // 4096
#define FULLMASK 0xffffffffu

// Scratch (allocation-free per harness rules)
__device__ float g_qkv[Bdim*Sdim*3*Edim];
__device__ float g_q[Bdim*Hdim*Sdim*HDdim];   // tf32-pre-rounded
__device__ float g_k[Bdim*Hdim*Sdim*HDdim];   // tf32-pre-rounded
__device__ float g_v[Bdim*Hdim*Sdim*HDdim];   // tf32-pre-rounded
__device__ float g_ctx[Bdim*Sdim*Edim];       // [b,s,h,d], tf32-pre-rounded
__device__ float g_hs_r[MROWS*Edim];          // hs rounded to tf32
__device__ float g_wqkv_r[3*Edim*Edim];       // w_qkv rounded
__device__ float g_wout_r[Edim*Edim];         // w_out rounded

__device__ __forceinline__ float to_tf32(float x) {
    uint32_t u;
    asm("cvt.rna.tf32.f32 %0, %1;" : "=r"(u) : "f"(x));
    return __uint_as_float(u);
}
__device__ __forceinline__ uint32_t f2u(float x) { return __float_as_uint(x); }
__device__ __forceinline__ uint32_t smaddr(const void* p) {
    return (uint32_t)__cvta_generic_to_shared(p);
}
__device__ __forceinline__ void cp_async16(uint32_t dst, const void* src) {
    asm volatile("cp.async.cg.shared.global [%0], [%1], 16;" :: "r"(dst), "l"(src));
}
__device__ __forceinline__ void cp_commit() {
    asm volatile("cp.async.commit_group;");
}
template<int N> __device__ __forceinline__ void cp_wait() {
    asm volatile("cp.async.wait_group %0;" :: "n"(N));
}

__device__ __forceinline__ void mma_tf32(float c[4],
    uint32_t a0, uint32_t a1, uint32_t a2, uint32_t a3,
    uint32_t b0, uint32_t b1)
{
    asm volatile(
        "mma.sync.aligned.m16n8k8.row.col.f32.tf32.tf32.f32 "
        "{%0,%1,%2,%3}, {%4,%5,%6,%7}, {%8,%9}, {%0,%1,%2,%3};"
        : "+f"(c[0]), "+f"(c[1]), "+f"(c[2]), "+f"(c[3])
        : "r"(a0), "r"(a1), "r"(a2), "r"(a3), "r"(b0), "r"(b1));
}

// ---------------------------------------------------------------------------
// Pre-round to tf32 (float4 granularity; all sizes divisible by 4)
// ---------------------------------------------------------------------------
__global__ __launch_bounds__(256) void round_tf32(
    const float* __restrict__ src, float* __restrict__ dst, int n4)
{
    int i = blockIdx.x * blockDim.x + threadIdx.x;
    if (i >= n4) return;
    float4 v = ((const float4*)src)[i];
    v.x = to_tf32(v.x); v.y = to_tf32(v.y);
    v.z = to_tf32(v.z); v.w = to_tf32(v.w);
    ((float4*)dst)[i] = v;
}

// ---------------------------------------------------------------------------
// TF32 GEMM, 2-stage cp.async pipeline: C[M,N] = A[M,K] @ W[N,K]^T
// Inputs PRE-ROUNDED to tf32 -> fragment loads are plain LDS (no CVT).
// BM=128, BN=128, BK=32, 256 threads (8 warps 4x2), warp tile 32x64.
// ---------------------------------------------------------------------------
#define AST 36
__global__ __launch_bounds__(256) void sgemm_tf32(
    const float* __restrict__ A, const float* __restrict__ W,
    float* __restrict__ C, int M, int N, int K)
{
    extern __shared__ float sm[];    // [stage][A(128*AST) | W(128*AST)]
    const int tid  = threadIdx.x;
    const int lane = tid & 31, wid = tid >> 5;
    const int gid  = lane >> 2, tig = lane & 3;
    const int wm   = (wid & 3) * 32;
    const int wn   = (wid >> 2) * 64;
    const int m0   = blockIdx.y * 128;
    const int n0   = blockIdx.x * 128;

    auto issue = [&](int st, int k0) {
        float* As = sm + st * (2 * 128 * AST);
        float* Ws = As + 128 * AST;
#pragma unroll
        for (int it = 0; it < 4; it++) {
            int idx = tid + it * 256;
            int r = idx >> 3, c4 = idx & 7;
            cp_async16(smaddr(As + r * AST + c4 * 4), A + (size_t)(m0 + r) * K + k0 + c4 * 4);
            cp_async16(smaddr(Ws + r * AST + c4 * 4), W + (size_t)(n0 + r) * K + k0 + c4 * 4);
        }
        cp_commit();
    };

    float c[2][8][4];
#pragma unroll
    for (int mi = 0; mi < 2; mi++)
#pragma unroll
        for (int ni = 0; ni < 8; ni++)
#pragma unroll
            for (int j = 0; j < 4; j++) c[mi][ni][j] = 0.0f;

    const int nt = K / 32;
    issue(0, 0);
    for (int t = 0; t < nt; t++) {
        if (t + 1 < nt) { issue((t + 1) & 1, (t + 1) * 32); cp_wait<1>(); }
        else            { cp_wait<0>(); }
        __syncthreads();
        const float* As = sm + (t & 1) * (2 * 128 * AST);
        const float* Ws = As + 128 * AST;

#pragma unroll
        for (int kk = 0; kk < 4; kk++) {
            const int kb = kk * 8;
            uint32_t a[2][4];
#pragma unroll
            for (int mi = 0; mi < 2; mi++) {
                int rb = wm + mi * 16;
                a[mi][0] = f2u(As[(rb + gid    ) * AST + kb + tig    ]);
                a[mi][1] = f2u(As[(rb + gid + 8) * AST + kb + tig    ]);
                a[mi][2] = f2u(As[(rb + gid    ) * AST + kb + tig + 4]);
                a[mi][3] = f2u(As[(rb + gid + 8) * AST + kb + tig + 4]);
            }
#pragma unroll
            for (int ni = 0; ni < 8; ni++) {
                uint32_t b0 = f2u(Ws[(wn + ni * 8 + gid) * AST + kb + tig    ]);
                uint32_t b1 = f2u(Ws[(wn + ni * 8 + gid) * AST + kb + tig + 4]);
                mma_tf32(c[0][ni], a[0][0], a[0][1], a[0][2], a[0][3], b0, b1);
                mma_tf32(c[1][ni], a[1][0], a[1][1], a[1][2], a[1][3], b0, b1);
            }
        }
        __syncthreads();
    }

#pragma unroll
    for (int mi = 0; mi < 2; mi++) {
#pragma unroll
        for (int ni = 0; ni < 8; ni++) {
            int r  = m0 + wm + mi * 16 + gid;
            int cc = n0 + wn + ni * 8 + 2 * tig;
            float2 v01 = make_float2(c[mi][ni][0], c[mi][ni][1]);
            float2 v23 = make_float2(c[mi][ni][2], c[mi][ni][3]);
            *(float2*)(C + (size_t)r * N + cc)       = v01;
            *(float2*)(C + (size_t)(r + 8) * N + cc) = v23;
        }
    }
}

// ---------------------------------------------------------------------------
// QKV de-interleave + RoPE (reference split order q, v, k); outputs tf32.
// ---------------------------------------------------------------------------
__global__ __launch_bounds__(256) void qkv_transform(const float* __restrict__ qkv)
{
    int idx = blockIdx.x * blockDim.x + threadIdx.x;
    if (idx >= Bdim * Sdim * Hdim * HDdim) return;
    int d = idx & (HDdim - 1);
    int h = (idx >> 6) & (Hdim - 1);
    int s = (idx >> 10) & (Sdim - 1);
    int b = idx >> 21;

    int mp = h >> 1, r = h & 1;
    const float* base = qkv + (size_t)(b * Sdim + s) * (3 * Edim) + mp * (3 * LOCAL) + r * HDdim;

    float qv = base[d];
    float vv = base[LOCAL + d];
    float kv = base[2 * LOCAL + d];

    if (d < RDdim) {
        int i = d >> 1;
        float inv = expf(-(float)i * 0.5756462732485115f);  // 10000^(-2i/RD)
        float ang = (float)s * inv;
        float sn, cs;
        sincosf(ang, &sn, &cs);
        int partner = d ^ 1;
        float qp = base[partner];
        float kp = base[2 * LOCAL + partner];
        if ((d & 1) == 0) {
            qv = qv * cs - qp * sn;
            kv = kv * cs - kp * sn;
        } else {
            qv = qv * cs + qp * sn;
            kv = kv * cs + kp * sn;
        }
    }
    size_t o = (size_t)((b * Hdim + h) * Sdim + s) * HDdim + d;
    g_q[o] = to_tf32(qv);
    g_k[o] = to_tf32(kv);
    g_v[o] = to_tf32(vv);
}

// ---------------------------------------------------------------------------
// Flash attention: 128-query tiles, 8 warps (16 rows each), 64-key tiles,
// 2-stage cp.async K/V double buffer, shuffle-transpose P (no smem P).
// NO min-blocks clause -> compiler free to keep ~96 accum floats in regs.
// ---------------------------------------------------------------------------
#define KST 68
#define TILE_F (64 * KST)
__global__ void __launch_bounds__(256) flash_mma()
{
    extern __shared__ float fsm[];
    const int qt  = 15 - (int)blockIdx.x;   // heavy tiles first
    const int bh  = blockIdx.y;
    const int tid = threadIdx.x;
    const int lane = tid & 31, w = tid >> 5;
    const int gid = lane >> 2, tig = lane & 3;

    const float* Kh = g_k + (size_t)bh * Sdim * HDdim;
    const float* Vh = g_v + (size_t)bh * Sdim * HDdim;

    auto issueKV = [&](int kt, int st) {
        const float* Kb = Kh + (size_t)kt * 64 * HDdim;
        const float* Vb = Vh + (size_t)kt * 64 * HDdim;
        float* Ks = fsm + st * (2 * TILE_F);
        float* Vs = Ks + TILE_F;
#pragma unroll
        for (int it = 0; it < 4; it++) {
            int idx = tid + it * 256;
            int r = idx >> 4, c4 = idx & 15;
            cp_async16(smaddr(Ks + r * KST + c4 * 4), Kb + (size_t)r * HDdim + c4 * 4);
            cp_async16(smaddr(Vs + r * KST + c4 * 4), Vb + (size_t)r * HDdim + c4 * 4);
        }
        cp_commit();
    };

    const int nk = 2 * qt + 2;
    issueKV(0, 0);

    // Q fragments straight from gmem (values already tf32-rounded)
    const float* Qb = g_q + ((size_t)bh * Sdim + qt * 128 + w * 16) * HDdim;
    uint32_t qa[8][4];
#pragma unroll
    for (int kk = 0; kk < 8; kk++) {
        qa[kk][0] = f2u(Qb[(size_t)(gid    ) * HDdim + kk * 8 + tig    ]);
        qa[kk][1] = f2u(Qb[(size_t)(gid + 8) * HDdim + kk * 8 + tig    ]);
        qa[kk][2] = f2u(Qb[(size_t)(gid    ) * HDdim + kk * 8 + tig + 4]);
        qa[kk][3] = f2u(Qb[(size_t)(gid + 8) * HDdim + kk * 8 + tig + 4]);
    }

    float m0r = -1e30f, m1r = -1e30f, l0 = 0.0f, l1 = 0.0f;
    float o[8][4];
#pragma unroll
    for (int ni = 0; ni < 8; ni++)
#pragma unroll
        for (int j = 0; j < 4; j++) o[ni][j] = 0.0f;

    const float scale = 0.125f;                 // 1/sqrt(64)
    const int row0 = qt * 128 + w * 16 + gid;   // thread's row (and row0+8)

    for (int kt = 0; kt < nk; kt++) {
        if (kt + 1 < nk) { issueKV(kt + 1, (kt + 1) & 1); cp_wait<1>(); }
        else             { cp_wait<0>(); }
        __syncthreads();
        const float* Ks = fsm + (kt & 1) * (2 * TILE_F);
        const float* Vs = Ks + TILE_F;

        // S = Q @ K^T
        float s[8][4];
#pragma unroll
        for (int ni = 0; ni < 8; ni++)
#pragma unroll
            for (int j = 0; j < 4; j++) s[ni][j] = 0.0f;
#pragma unroll
        for (int kk = 0; kk < 8; kk++) {
            int kb = kk * 8;
#pragma unroll
            for (int ni = 0; ni < 8; ni++) {
                uint32_t b0 = f2u(Ks[(ni * 8 + gid) * KST + kb + tig    ]);
                uint32_t b1 = f2u(Ks[(ni * 8 + gid) * KST + kb + tig + 4]);
                mma_tf32(s[ni], qa[kk][0], qa[kk][1], qa[kk][2], qa[kk][3], b0, b1);
            }
        }

        // scale + causal mask (only last two tiles can be partial)
        if (kt >= 2 * qt) {
#pragma unroll
            for (int ni = 0; ni < 8; ni++)
#pragma unroll
                for (int j = 0; j < 4; j++) {
                    int col  = kt * 64 + ni * 8 + 2 * tig + (j & 1);
                    int rowg = row0 + ((j >= 2) ? 8 : 0);
                    s[ni][j] = (col > rowg) ? -1e9f : s[ni][j] * scale;
                }
        } else {
#pragma unroll
            for (int ni = 0; ni < 8; ni++)
#pragma unroll
                for (int j = 0; j < 4; j++) s[ni][j] *= scale;
        }

        // online softmax (rows gid, gid+8)
        float mx0 = -1e30f, mx1 = -1e30f;
#pragma unroll
        for (int ni = 0; ni < 8; ni++) {
            mx0 = fmaxf(mx0, fmaxf(s[ni][0], s[ni][1]));
            mx1 = fmaxf(mx1, fmaxf(s[ni][2], s[ni][3]));
        }
        mx0 = fmaxf(mx0, __shfl_xor_sync(FULLMASK, mx0, 1));
        mx0 = fmaxf(mx0, __shfl_xor_sync(FULLMASK, mx0, 2));
        mx1 = fmaxf(mx1, __shfl_xor_sync(FULLMASK, mx1, 1));
        mx1 = fmaxf(mx1, __shfl_xor_sync(FULLMASK, mx1, 2));

        float mn0 = fmaxf(m0r, mx0), mn1 = fmaxf(m1r, mx1);
        float al0 = __expf(m0r - mn0), al1 = __expf(m1r - mn1);
        float rs0 = 0.0f, rs1 = 0.0f;
#pragma unroll
        for (int ni = 0; ni < 8; ni++) {
            float p0 = __expf(s[ni][0] - mn0); s[ni][0] = p0; rs0 += p0;
            float p1 = __expf(s[ni][1] - mn0); s[ni][1] = p1; rs0 += p1;
            float p2 = __expf(s[ni][2] - mn1); s[ni][2] = p2; rs1 += p2;
            float p3 = __expf(s[ni][3] - mn1); s[ni][3] = p3; rs1 += p3;
        }
        rs0 += __shfl_xor_sync(FULLMASK, rs0, 1);
        rs0 += __shfl_xor_sync(FULLMASK, rs0, 2);
        rs1 += __shfl_xor_sync(FULLMASK, rs1, 1);
        rs1 += __shfl_xor_sync(FULLMASK, rs1, 2);

        l0 = l0 * al0 + rs0;  l1 = l1 * al1 + rs1;
        m0r = mn0;  m1r = mn1;
#pragma unroll
        for (int ni = 0; ni < 8; ni++) {
            o[ni][0] *= al0; o[ni][1] *= al0;
            o[ni][2] *= al1; o[ni][3] *= al1;
        }

        // O += P @ V : C-frag -> A-frag via register shuffles
        const int src0 = (lane & 28) | (tig >> 1);
        const int src1 = src0 + 2;
        const bool odd = (tig & 1);
#pragma unroll
        for (int kk = 0; kk < 8; kk++) {
            float v00 = __shfl_sync(FULLMASK, s[kk][0], src0);
            float v01 = __shfl_sync(FULLMASK, s[kk][1], src0);
            float v10 = __shfl_sync(FULLMASK, s[kk][2], src0);
            float v11 = __shfl_sync(FULLMASK, s[kk][3], src0);
            float u00 = __shfl_sync(FULLMASK, s[kk][0], src1);
            float u01 = __shfl_sync(FULLMASK, s[kk][1], src1);
            float u10 = __shfl_sync(FULLMASK, s[kk][2], src1);
            float u11 = __shfl_sync(FULLMASK, s[kk][3], src1);
            uint32_t pa0 = f2u(to_tf32(odd ? v01 : v00));
            uint32_t pa1 = f2u(to_tf32(odd ? v11 : v10));
            uint32_t pa2 = f2u(to_tf32(odd ? u01 : u00));
            uint32_t pa3 = f2u(to_tf32(odd ? u11 : u10));
            int kb = kk * 8;
#pragma unroll
            for (int ni = 0; ni < 8; ni++) {
                uint32_t b0 = f2u(Vs[(kb + tig    ) * KST + ni * 8 + gid]);
                uint32_t b1 = f2u(Vs[(kb + tig + 4) * KST + ni * 8 + gid]);
                mma_tf32(o[ni], pa0, pa1, pa2, pa3, b0, b1);
            }
        }
        __syncthreads();
    }

    // epilogue -> g_ctx[b, s, h, d] (tf32-rounded for the out-proj GEMM)
    const int b = bh >> 4, h = bh & 15;
    const float inv0 = 1.0f / l0, inv1 = 1.0f / l1;
#pragma unroll
    for (int ni = 0; ni < 8; ni++) {
        int d0 = ni * 8 + 2 * tig;
        float2 v01 = make_float2(to_tf32(o[ni][0] * inv0), to_tf32(o[ni][1] * inv0));
        float2 v23 = make_float2(to_tf32(o[ni][2] * inv1), to_tf32(o[ni][3] * inv1));
        *(float2*)(g_ctx + (size_t)((b * Sdim + row0    ) * Hdim + h) * HDdim + d0) = v01;
        *(float2*)(g_ctx + (size_t)((b * Sdim + row0 + 8) * Hdim + h) * HDdim + d0) = v23;
    }
}

// ---------------------------------------------------------------------------
extern "C" void kernel_launch(void* const* d_in, const int* in_sizes, int n_in,
                              void* d_out, int out_size)
{
    const float* hs    = (const float*)d_in[0];   // [B,S,E]
    const float* w_qkv = (const float*)d_in[1];   // [3E,E]
    const float* w_out = (const float*)d_in[2];   // [E,E]
    float* out = (float*)d_out;                   // [B,S,E]

    float *p_qkv, *p_ctx, *p_hs, *p_wqkv, *p_wout;
    cudaGetSymbolAddress((void**)&p_qkv,  g_qkv);
    cudaGetSymbolAddress((void**)&p_ctx,  g_ctx);
    cudaGetSymbolAddress((void**)&p_hs,   g_hs_r);
    cudaGetSymbolAddress((void**)&p_wqkv, g_wqkv_r);
    cudaGetSymbolAddress((void**)&p_wout, g_wout_r);

    const int GS = 4 * 128 * AST * sizeof(float);   // 73728 B (2 stages A+W)
    const int FS = 4 * TILE_F * sizeof(float);      // 69632 B (2 stages K+V)
    cudaFuncSetAttribute(sgemm_tf32, cudaFuncAttributeMaxDynamicSharedMemorySize, GS);
    cudaFuncSetAttribute(flash_mma,  cudaFuncAttributeMaxDynamicSharedMemorySize, FS);

    // 0) pre-round inputs to tf32 (removes CVTs from GEMM hot loops)
    {
        int n4;
        n4 = MROWS * Edim / 4;
        round_tf32<<<(n4 + 255) / 256, 256>>>(hs, p_hs, n4);
        n4 = 3 * Edim * Edim / 4;
        round_tf32<<<(n4 + 255) / 256, 256>>>(w_qkv, p_wqkv, n4);
        n4 = Edim * Edim / 4;
        round_tf32<<<(n4 + 255) / 256, 256>>>(w_out, p_wout, n4);
    }
    // 1) QKV projection: [4096,1024] @ [3072,1024]^T
    {
        dim3 grid(3 * Edim / 128, MROWS / 128);
        sgemm_tf32<<<grid, 256, GS>>>(p_hs, p_wqkv, p_qkv, MROWS, 3 * Edim, Edim);
    }
    // 2) split + RoPE (tf32 outputs)
    {
        int total = Bdim * Sdim * Hdim * HDdim;
        qkv_transform<<<(total + 255) / 256, 256>>>(p_qkv);
    }
    // 3) flash attention (128-query tiles, no reg cap)
    {
        dim3 grid(Sdim / 128, Bdim * Hdim);
        flash_mma<<<grid, 256, FS>>>();
    }
    // 4) output projection: [4096,1024] @ [1024,1024]^T
    {
        dim3 grid(Edim / 128, MROWS / 128);
        sgemm_tf32<<<grid, 256, GS>>>(p_ctx, p_wout, out, MROWS, Edim, Edim);
    }
}

// round 8
// speedup vs baseline: 1.1258x; 1.0336x over previous
#include <cuda_runtime.h>
#include <math.h>
#include <stdint.h>

#define Bdim 2
#define Sdim 2048
#define Edim 1024
#define Hdim 16
#define HDdim 64
#define RDdim 32
#define MROWS (Bdim*Sdim)  // 4096
#define FULLMASK 0xffffffffu

// Scratch (allocation-free per harness rules)
__device__ float g_q[Bdim*Hdim*Sdim*HDdim];   // tf32-pre-rounded, [b,h,s,d]
__device__ float g_k[Bdim*Hdim*Sdim*HDdim];
__device__ float g_v[Bdim*Hdim*Sdim*HDdim];
__device__ float g_ctx[Bdim*Sdim*Edim];       // [b,s,h,d], tf32-pre-rounded
__device__ float g_hs_r[MROWS*Edim];          // hs rounded to tf32
__device__ float g_wqkv_r[3*Edim*Edim];       // w_qkv rounded
__device__ float g_wout_r[Edim*Edim];         // w_out rounded

__device__ __forceinline__ float to_tf32(float x) {
    uint32_t u;
    asm("cvt.rna.tf32.f32 %0, %1;" : "=r"(u) : "f"(x));
    return __uint_as_float(u);
}
__device__ __forceinline__ uint32_t f2u(float x) { return __float_as_uint(x); }
__device__ __forceinline__ uint32_t smaddr(const void* p) {
    return (uint32_t)__cvta_generic_to_shared(p);
}
__device__ __forceinline__ void cp_async16(uint32_t dst, const void* src) {
    asm volatile("cp.async.cg.shared.global [%0], [%1], 16;" :: "r"(dst), "l"(src));
}
__device__ __forceinline__ void cp_commit() {
    asm volatile("cp.async.commit_group;");
}
template<int N> __device__ __forceinline__ void cp_wait() {
    asm volatile("cp.async.wait_group %0;" :: "n"(N));
}

__device__ __forceinline__ void mma_tf32(float c[4],
    uint32_t a0, uint32_t a1, uint32_t a2, uint32_t a3,
    uint32_t b0, uint32_t b1)
{
    asm volatile(
        "mma.sync.aligned.m16n8k8.row.col.f32.tf32.tf32.f32 "
        "{%0,%1,%2,%3}, {%4,%5,%6,%7}, {%8,%9}, {%0,%1,%2,%3};"
        : "+f"(c[0]), "+f"(c[1]), "+f"(c[2]), "+f"(c[3])
        : "r"(a0), "r"(a1), "r"(a2), "r"(a3), "r"(b0), "r"(b1));
}

// ---------------------------------------------------------------------------
// Pre-round to tf32 (float4 granularity)
// ---------------------------------------------------------------------------
__global__ __launch_bounds__(256) void round_tf32(
    const float* __restrict__ src, float* __restrict__ dst, int n4)
{
    int i = blockIdx.x * blockDim.x + threadIdx.x;
    if (i >= n4) return;
    float4 v = ((const float4*)src)[i];
    v.x = to_tf32(v.x); v.y = to_tf32(v.y);
    v.z = to_tf32(v.z); v.w = to_tf32(v.w);
    ((float4*)dst)[i] = v;
}

// ---------------------------------------------------------------------------
// TF32 GEMM, 2-stage cp.async pipeline: C[M,N] = A[M,K] @ W[N,K]^T
// BM=128, BN=128, BK=32, 256 threads (8 warps 4x2), warp tile 32x64.
// DO_QKV=1: fused split + RoPE epilogue writing q/k/v in [b,h,s,d] (tf32).
//   Column tile (128 wide) lies in ONE part: part = blockIdx.x % 3
//   (0=q, 1=v, 2=k — reference split order!), mp = blockIdx.x / 3.
// DO_QKV=0: plain epilogue to C.
// ---------------------------------------------------------------------------
#define AST 36
template<int DO_QKV>
__global__ __launch_bounds__(256) void sgemm_tf32(
    const float* __restrict__ A, const float* __restrict__ W,
    float* __restrict__ C, int M, int N, int K)
{
    extern __shared__ float sm[];    // [stage][A(128*AST) | W(128*AST)]
    const int tid  = threadIdx.x;
    const int lane = tid & 31, wid = tid >> 5;
    const int gid  = lane >> 2, tig = lane & 3;
    const int wm   = (wid & 3) * 32;
    const int wn   = (wid >> 2) * 64;
    const int m0   = blockIdx.y * 128;
    const int n0   = blockIdx.x * 128;

    auto issue = [&](int st, int k0) {
        float* As = sm + st * (2 * 128 * AST);
        float* Ws = As + 128 * AST;
#pragma unroll
        for (int it = 0; it < 4; it++) {
            int idx = tid + it * 256;
            int r = idx >> 3, c4 = idx & 7;
            cp_async16(smaddr(As + r * AST + c4 * 4), A + (size_t)(m0 + r) * K + k0 + c4 * 4);
            cp_async16(smaddr(Ws + r * AST + c4 * 4), W + (size_t)(n0 + r) * K + k0 + c4 * 4);
        }
        cp_commit();
    };

    float c[2][8][4];
#pragma unroll
    for (int mi = 0; mi < 2; mi++)
#pragma unroll
        for (int ni = 0; ni < 8; ni++)
#pragma unroll
            for (int j = 0; j < 4; j++) c[mi][ni][j] = 0.0f;

    const int nt = K / 32;
    issue(0, 0);
    for (int t = 0; t < nt; t++) {
        if (t + 1 < nt) { issue((t + 1) & 1, (t + 1) * 32); cp_wait<1>(); }
        else            { cp_wait<0>(); }
        __syncthreads();
        const float* As = sm + (t & 1) * (2 * 128 * AST);
        const float* Ws = As + 128 * AST;

#pragma unroll
        for (int kk = 0; kk < 4; kk++) {
            const int kb = kk * 8;
            uint32_t a[2][4];
#pragma unroll
            for (int mi = 0; mi < 2; mi++) {
                int rb = wm + mi * 16;
                a[mi][0] = f2u(As[(rb + gid    ) * AST + kb + tig    ]);
                a[mi][1] = f2u(As[(rb + gid + 8) * AST + kb + tig    ]);
                a[mi][2] = f2u(As[(rb + gid    ) * AST + kb + tig + 4]);
                a[mi][3] = f2u(As[(rb + gid + 8) * AST + kb + tig + 4]);
            }
#pragma unroll
            for (int ni = 0; ni < 8; ni++) {
                uint32_t b0 = f2u(Ws[(wn + ni * 8 + gid) * AST + kb + tig    ]);
                uint32_t b1 = f2u(Ws[(wn + ni * 8 + gid) * AST + kb + tig + 4]);
                mma_tf32(c[0][ni], a[0][0], a[0][1], a[0][2], a[0][3], b0, b1);
                mma_tf32(c[1][ni], a[1][0], a[1][1], a[1][2], a[1][3], b0, b1);
            }
        }
        __syncthreads();
    }

    if (DO_QKV) {
        // fused split + RoPE epilogue
        const int part = (int)blockIdx.x % 3;       // 0=q, 1=v, 2=k
        const int mp   = (int)blockIdx.x / 3;
        float* dst = (part == 0) ? g_q : (part == 1) ? g_v : g_k;
#pragma unroll
        for (int mi = 0; mi < 2; mi++) {
#pragma unroll
            for (int ni = 0; ni < 8; ni++) {
                int c_local = wn + ni * 8 + 2 * tig;    // even, in [0,128)
                int rhead = c_local >> 6;
                int d = c_local & 63;
                int h = mp * 2 + rhead;
                bool rope = (part != 1) && (d < RDdim);
                float inv = 0.0f;
                if (rope) {
                    int fi = d >> 1;
                    inv = exp2f(-(float)fi * 0.8304820237218405f); // 10000^(-2i/RD)
                }
#pragma unroll
                for (int half = 0; half < 2; half++) {
                    int row = m0 + wm + mi * 16 + gid + half * 8;
                    float v0 = c[mi][ni][half * 2];
                    float v1 = c[mi][ni][half * 2 + 1];
                    int b  = row >> 11;
                    int sl = row & 2047;
                    if (rope) {
                        float ang = (float)sl * inv;
                        float sn, cs;
                        sincosf(ang, &sn, &cs);
                        float e = v0 * cs - v1 * sn;
                        float o = v1 * cs + v0 * sn;
                        v0 = e; v1 = o;
                    }
                    float2 st = make_float2(to_tf32(v0), to_tf32(v1));
                    *(float2*)(dst + ((size_t)(b * Hdim + h) * Sdim + sl) * HDdim + d) = st;
                }
            }
        }
    } else {
#pragma unroll
        for (int mi = 0; mi < 2; mi++) {
#pragma unroll
            for (int ni = 0; ni < 8; ni++) {
                int r  = m0 + wm + mi * 16 + gid;
                int cc = n0 + wn + ni * 8 + 2 * tig;
                float2 v01 = make_float2(c[mi][ni][0], c[mi][ni][1]);
                float2 v23 = make_float2(c[mi][ni][2], c[mi][ni][3]);
                *(float2*)(C + (size_t)r * N + cc)       = v01;
                *(float2*)(C + (size_t)(r + 8) * N + cc) = v23;
            }
        }
    }
}

// ---------------------------------------------------------------------------
// Flash attention: 128-query tiles, 8 warps, 128-KEY tiles, 2-stage cp.async
// double buffer, shuffle-transpose P. smem = 2 x (Ks 128x68 + Vs 128x68).
// ---------------------------------------------------------------------------
#define KST 68
#define KTILE 128
#define TILE_F (KTILE * KST)
__global__ void __launch_bounds__(256) flash_mma()
{
    extern __shared__ float fsm[];
    const int qt  = 15 - (int)blockIdx.x;   // heavy tiles first
    const int bh  = blockIdx.y;
    const int tid = threadIdx.x;
    const int lane = tid & 31, w = tid >> 5;
    const int gid = lane >> 2, tig = lane & 3;

    const float* Kh = g_k + (size_t)bh * Sdim * HDdim;
    const float* Vh = g_v + (size_t)bh * Sdim * HDdim;

    auto issueKV = [&](int kt, int st) {
        const float* Kb = Kh + (size_t)kt * KTILE * HDdim;
        const float* Vb = Vh + (size_t)kt * KTILE * HDdim;
        float* Ks = fsm + st * (2 * TILE_F);
        float* Vs = Ks + TILE_F;
#pragma unroll
        for (int it = 0; it < 8; it++) {
            int idx = tid + it * 256;          // 0..2047
            int r = idx >> 4, c4 = idx & 15;
            cp_async16(smaddr(Ks + r * KST + c4 * 4), Kb + (size_t)r * HDdim + c4 * 4);
            cp_async16(smaddr(Vs + r * KST + c4 * 4), Vb + (size_t)r * HDdim + c4 * 4);
        }
        cp_commit();
    };

    const int nk = qt + 1;
    issueKV(0, 0);

    // Q fragments straight from gmem (values already tf32-rounded)
    const float* Qb = g_q + ((size_t)bh * Sdim + qt * 128 + w * 16) * HDdim;
    uint32_t qa[8][4];
#pragma unroll
    for (int kk = 0; kk < 8; kk++) {
        qa[kk][0] = f2u(Qb[(size_t)(gid    ) * HDdim + kk * 8 + tig    ]);
        qa[kk][1] = f2u(Qb[(size_t)(gid + 8) * HDdim + kk * 8 + tig    ]);
        qa[kk][2] = f2u(Qb[(size_t)(gid    ) * HDdim + kk * 8 + tig + 4]);
        qa[kk][3] = f2u(Qb[(size_t)(gid + 8) * HDdim + kk * 8 + tig + 4]);
    }

    float m0r = -1e30f, m1r = -1e30f, l0 = 0.0f, l1 = 0.0f;
    float o[8][4];
#pragma unroll
    for (int ni = 0; ni < 8; ni++)
#pragma unroll
        for (int j = 0; j < 4; j++) o[ni][j] = 0.0f;

    const float scale = 0.125f;                 // 1/sqrt(64)
    const int row0 = qt * 128 + w * 16 + gid;   // thread's rows (row0, row0+8)

    for (int kt = 0; kt < nk; kt++) {
        if (kt + 1 < nk) { issueKV(kt + 1, (kt + 1) & 1); cp_wait<1>(); }
        else             { cp_wait<0>(); }
        __syncthreads();
        const float* Ks = fsm + (kt & 1) * (2 * TILE_F);
        const float* Vs = Ks + TILE_F;

        // S = Q @ K^T  (16 rows x 128 keys per warp)
        float s[16][4];
#pragma unroll
        for (int ni = 0; ni < 16; ni++)
#pragma unroll
            for (int j = 0; j < 4; j++) s[ni][j] = 0.0f;
#pragma unroll
        for (int kk = 0; kk < 8; kk++) {
            int kb = kk * 8;
#pragma unroll
            for (int ni = 0; ni < 16; ni++) {
                uint32_t b0 = f2u(Ks[(ni * 8 + gid) * KST + kb + tig    ]);
                uint32_t b1 = f2u(Ks[(ni * 8 + gid) * KST + kb + tig + 4]);
                mma_tf32(s[ni], qa[kk][0], qa[kk][1], qa[kk][2], qa[kk][3], b0, b1);
            }
        }

        // scale + causal mask (only the diagonal tile is partial)
        if (kt == qt) {
#pragma unroll
            for (int ni = 0; ni < 16; ni++)
#pragma unroll
                for (int j = 0; j < 4; j++) {
                    int col  = kt * KTILE + ni * 8 + 2 * tig + (j & 1);
                    int rowg = row0 + ((j >= 2) ? 8 : 0);
                    s[ni][j] = (col > rowg) ? -1e9f : s[ni][j] * scale;
                }
        } else {
#pragma unroll
            for (int ni = 0; ni < 16; ni++)
#pragma unroll
                for (int j = 0; j < 4; j++) s[ni][j] *= scale;
        }

        // online softmax (rows gid, gid+8)
        float mx0 = -1e30f, mx1 = -1e30f;
#pragma unroll
        for (int ni = 0; ni < 16; ni++) {
            mx0 = fmaxf(mx0, fmaxf(s[ni][0], s[ni][1]));
            mx1 = fmaxf(mx1, fmaxf(s[ni][2], s[ni][3]));
        }
        mx0 = fmaxf(mx0, __shfl_xor_sync(FULLMASK, mx0, 1));
        mx0 = fmaxf(mx0, __shfl_xor_sync(FULLMASK, mx0, 2));
        mx1 = fmaxf(mx1, __shfl_xor_sync(FULLMASK, mx1, 1));
        mx1 = fmaxf(mx1, __shfl_xor_sync(FULLMASK, mx1, 2));

        float mn0 = fmaxf(m0r, mx0), mn1 = fmaxf(m1r, mx1);
        float al0 = __expf(m0r - mn0), al1 = __expf(m1r - mn1);
        float rs0 = 0.0f, rs1 = 0.0f;
#pragma unroll
        for (int ni = 0; ni < 16; ni++) {
            float p0 = __expf(s[ni][0] - mn0); s[ni][0] = p0; rs0 += p0;
            float p1 = __expf(s[ni][1] - mn0); s[ni][1] = p1; rs0 += p1;
            float p2 = __expf(s[ni][2] - mn1); s[ni][2] = p2; rs1 += p2;
            float p3 = __expf(s[ni][3] - mn1); s[ni][3] = p3; rs1 += p3;
        }
        rs0 += __shfl_xor_sync(FULLMASK, rs0, 1);
        rs0 += __shfl_xor_sync(FULLMASK, rs0, 2);
        rs1 += __shfl_xor_sync(FULLMASK, rs1, 1);
        rs1 += __shfl_xor_sync(FULLMASK, rs1, 2);

        l0 = l0 * al0 + rs0;  l1 = l1 * al1 + rs1;
        m0r = mn0;  m1r = mn1;
#pragma unroll
        for (int ni = 0; ni < 8; ni++) {
            o[ni][0] *= al0; o[ni][1] *= al0;
            o[ni][2] *= al1; o[ni][3] *= al1;
        }

        // O += P @ V : C-frag -> A-frag via register shuffles (16 k-chunks)
        const int src0 = (lane & 28) | (tig >> 1);
        const int src1 = src0 + 2;
        const bool odd = (tig & 1);
#pragma unroll
        for (int kk = 0; kk < 16; kk++) {
            float v00 = __shfl_sync(FULLMASK, s[kk][0], src0);
            float v01 = __shfl_sync(FULLMASK, s[kk][1], src0);
            float v10 = __shfl_sync(FULLMASK, s[kk][2], src0);
            float v11 = __shfl_sync(FULLMASK, s[kk][3], src0);
            float u00 = __shfl_sync(FULLMASK, s[kk][0], src1);
            float u01 = __shfl_sync(FULLMASK, s[kk][1], src1);
            float u10 = __shfl_sync(FULLMASK, s[kk][2], src1);
            float u11 = __shfl_sync(FULLMASK, s[kk][3], src1);
            uint32_t pa0 = f2u(to_tf32(odd ? v01 : v00));
            uint32_t pa1 = f2u(to_tf32(odd ? v11 : v10));
            uint32_t pa2 = f2u(to_tf32(odd ? u01 : u00));
            uint32_t pa3 = f2u(to_tf32(odd ? u11 : u10));
            int kb = kk * 8;
#pragma unroll
            for (int ni = 0; ni < 8; ni++) {
                uint32_t b0 = f2u(Vs[(kb + tig    ) * KST + ni * 8 + gid]);
                uint32_t b1 = f2u(Vs[(kb + tig + 4) * KST + ni * 8 + gid]);
                mma_tf32(o[ni], pa0, pa1, pa2, pa3, b0, b1);
            }
        }
        __syncthreads();
    }

    // epilogue -> g_ctx[b, s, h, d] (tf32-rounded for the out-proj GEMM)
    const int b = bh >> 4, h = bh & 15;
    const float inv0 = 1.0f / l0, inv1 = 1.0f / l1;
#pragma unroll
    for (int ni = 0; ni < 8; ni++) {
        int d0 = ni * 8 + 2 * tig;
        float2 v01 = make_float2(to_tf32(o[ni][0] * inv0), to_tf32(o[ni][1] * inv0));
        float2 v23 = make_float2(to_tf32(o[ni][2] * inv1), to_tf32(o[ni][3] * inv1));
        *(float2*)(g_ctx + (size_t)((b * Sdim + row0    ) * Hdim + h) * HDdim + d0) = v01;
        *(float2*)(g_ctx + (size_t)((b * Sdim + row0 + 8) * Hdim + h) * HDdim + d0) = v23;
    }
}

// ---------------------------------------------------------------------------
extern "C" void kernel_launch(void* const* d_in, const int* in_sizes, int n_in,
                              void* d_out, int out_size)
{
    const float* hs    = (const float*)d_in[0];   // [B,S,E]
    const float* w_qkv = (const float*)d_in[1];   // [3E,E]
    const float* w_out = (const float*)d_in[2];   // [E,E]
    float* out = (float*)d_out;                   // [B,S,E]

    float *p_ctx, *p_hs, *p_wqkv, *p_wout;
    cudaGetSymbolAddress((void**)&p_ctx,  g_ctx);
    cudaGetSymbolAddress((void**)&p_hs,   g_hs_r);
    cudaGetSymbolAddress((void**)&p_wqkv, g_wqkv_r);
    cudaGetSymbolAddress((void**)&p_wout, g_wout_r);

    const int GS = 4 * 128 * AST * sizeof(float);   // 73728 B (2 stages A+W)
    const int FS = 4 * TILE_F * sizeof(float);      // 139264 B (2 stages K+V)
    cudaFuncSetAttribute(sgemm_tf32<1>, cudaFuncAttributeMaxDynamicSharedMemorySize, GS);
    cudaFuncSetAttribute(sgemm_tf32<0>, cudaFuncAttributeMaxDynamicSharedMemorySize, GS);
    cudaFuncSetAttribute(flash_mma,     cudaFuncAttributeMaxDynamicSharedMemorySize, FS);

    // 0) pre-round inputs to tf32
    {
        int n4;
        n4 = MROWS * Edim / 4;
        round_tf32<<<(n4 + 255) / 256, 256>>>(hs, p_hs, n4);
        n4 = 3 * Edim * Edim / 4;
        round_tf32<<<(n4 + 255) / 256, 256>>>(w_qkv, p_wqkv, n4);
        n4 = Edim * Edim / 4;
        round_tf32<<<(n4 + 255) / 256, 256>>>(w_out, p_wout, n4);
    }
    // 1) QKV projection with FUSED split + RoPE epilogue -> g_q/g_k/g_v
    {
        dim3 grid(3 * Edim / 128, MROWS / 128);
        sgemm_tf32<1><<<grid, 256, GS>>>(p_hs, p_wqkv, nullptr, MROWS, 3 * Edim, Edim);
    }
    // 2) flash attention (128-query x 128-key tiles)
    {
        dim3 grid(Sdim / 128, Bdim * Hdim);
        flash_mma<<<grid, 256, FS>>>();
    }
    // 3) output projection: [4096,1024] @ [1024,1024]^T
    {
        dim3 grid(Edim / 128, MROWS / 128);
        sgemm_tf32<0><<<grid, 256, GS>>>(p_ctx, p_wout, out, MROWS, Edim, Edim);
    }
}

// round 9
// speedup vs baseline: 1.1928x; 1.0595x over previous
#include <cuda_runtime.h>
#include <math.h>
#include <stdint.h>

#define Bdim 2
#define Sdim 2048
#define Edim 1024
#define Hdim 16
#define HDdim 64
#define RDdim 32
#define MROWS (Bdim*Sdim)  // 4096
#define FULLMASK 0xffffffffu

// Scratch (allocation-free per harness rules)
__device__ float g_q[Bdim*Hdim*Sdim*HDdim];   // tf32-pre-rounded, [b,h,s,d]
__device__ float g_k[Bdim*Hdim*Sdim*HDdim];
__device__ float g_v[Bdim*Hdim*Sdim*HDdim];
__device__ float g_ctx[Bdim*Sdim*Edim];       // [b,s,h,d], tf32-pre-rounded
__device__ float g_hs_r[MROWS*Edim];          // hs rounded to tf32
__device__ float g_wqkv_r[3*Edim*Edim];       // w_qkv rounded
__device__ float g_wout_r[Edim*Edim];         // w_out rounded

__device__ __forceinline__ float to_tf32(float x) {
    uint32_t u;
    asm("cvt.rna.tf32.f32 %0, %1;" : "=r"(u) : "f"(x));
    return __uint_as_float(u);
}
__device__ __forceinline__ uint32_t f2u(float x) { return __float_as_uint(x); }
__device__ __forceinline__ uint32_t smaddr(const void* p) {
    return (uint32_t)__cvta_generic_to_shared(p);
}
__device__ __forceinline__ void cp_async16(uint32_t dst, const void* src) {
    asm volatile("cp.async.cg.shared.global [%0], [%1], 16;" :: "r"(dst), "l"(src));
}
__device__ __forceinline__ void cp_commit() {
    asm volatile("cp.async.commit_group;");
}
template<int N> __device__ __forceinline__ void cp_wait() {
    asm volatile("cp.async.wait_group %0;" :: "n"(N));
}

// ldmatrix x4: four 8x8 b16 matrices == tf32 fragment groups (see theory)
__device__ __forceinline__ void ldsm_x4(uint32_t& r0, uint32_t& r1,
                                        uint32_t& r2, uint32_t& r3, uint32_t addr)
{
    asm volatile("ldmatrix.sync.aligned.m8n8.x4.shared.b16 {%0,%1,%2,%3}, [%4];"
        : "=r"(r0), "=r"(r1), "=r"(r2), "=r"(r3) : "r"(addr));
}

__device__ __forceinline__ void mma_tf32(float c[4],
    uint32_t a0, uint32_t a1, uint32_t a2, uint32_t a3,
    uint32_t b0, uint32_t b1)
{
    asm volatile(
        "mma.sync.aligned.m16n8k8.row.col.f32.tf32.tf32.f32 "
        "{%0,%1,%2,%3}, {%4,%5,%6,%7}, {%8,%9}, {%0,%1,%2,%3};"
        : "+f"(c[0]), "+f"(c[1]), "+f"(c[2]), "+f"(c[3])
        : "r"(a0), "r"(a1), "r"(a2), "r"(a3), "r"(b0), "r"(b1));
}

// ---------------------------------------------------------------------------
// Pre-round to tf32
// ---------------------------------------------------------------------------
__global__ __launch_bounds__(256) void round_tf32(
    const float* __restrict__ src, float* __restrict__ dst, int n4)
{
    int i = blockIdx.x * blockDim.x + threadIdx.x;
    if (i >= n4) return;
    float4 v = ((const float4*)src)[i];
    v.x = to_tf32(v.x); v.y = to_tf32(v.y);
    v.z = to_tf32(v.z); v.w = to_tf32(v.w);
    ((float4*)dst)[i] = v;
}

// ---------------------------------------------------------------------------
// TF32 GEMM, 2-stage cp.async pipeline, LDSM fragment loads.
// BM=128, BN=128, BK=32, 256 threads (8 warps 4x2), warp tile 32x64.
// DO_QKV=1: fused split + RoPE epilogue (part = blockIdx.x % 3: 0=q,1=v,2=k).
// ---------------------------------------------------------------------------
#define AST 36
template<int DO_QKV>
__global__ __launch_bounds__(256) void sgemm_tf32(
    const float* __restrict__ A, const float* __restrict__ W,
    float* __restrict__ C, int M, int N, int K)
{
    extern __shared__ float sm[];    // [stage][A(128*AST) | W(128*AST)]
    const int tid  = threadIdx.x;
    const int lane = tid & 31, wid = tid >> 5;
    const int gid  = lane >> 2, tig = lane & 3;
    const int wm   = (wid & 3) * 32;
    const int wn   = (wid >> 2) * 64;
    const int m0   = blockIdx.y * 128;
    const int n0   = blockIdx.x * 128;

    // ldmatrix per-thread address pieces: matrix index m = lane>>3, row = lane&7
    const int lrow = lane & 7, lmat = lane >> 3;
    // A x4 (per mi): matrices {rows0-7,k0-3},{rows8-15,k0-3},{rows0-7,k4-7},{rows8-15,k4-7}
    const int a_row = (lmat & 1) * 8 + lrow;
    const int a_kof = (lmat >> 1) * 4;
    // B x4 (per ni-pair): matrices {ni,k0-3},{ni,k4-7},{ni+1,k0-3},{ni+1,k4-7}
    const int b_ni  = lmat >> 1;            // 0 or 1 within pair
    const int b_kof = (lmat & 1) * 4;

    auto issue = [&](int st, int k0) {
        float* As = sm + st * (2 * 128 * AST);
        float* Ws = As + 128 * AST;
#pragma unroll
        for (int it = 0; it < 4; it++) {
            int idx = tid + it * 256;
            int r = idx >> 3, c4 = idx & 7;
            cp_async16(smaddr(As + r * AST + c4 * 4), A + (size_t)(m0 + r) * K + k0 + c4 * 4);
            cp_async16(smaddr(Ws + r * AST + c4 * 4), W + (size_t)(n0 + r) * K + k0 + c4 * 4);
        }
        cp_commit();
    };

    float c[2][8][4];
#pragma unroll
    for (int mi = 0; mi < 2; mi++)
#pragma unroll
        for (int ni = 0; ni < 8; ni++)
#pragma unroll
            for (int j = 0; j < 4; j++) c[mi][ni][j] = 0.0f;

    const int nt = K / 32;
    issue(0, 0);
    for (int t = 0; t < nt; t++) {
        if (t + 1 < nt) { issue((t + 1) & 1, (t + 1) * 32); cp_wait<1>(); }
        else            { cp_wait<0>(); }
        __syncthreads();
        const float* As = sm + (t & 1) * (2 * 128 * AST);
        const float* Ws = As + 128 * AST;

        // per-stage ldmatrix base addresses
        uint32_t aaddr[2], baddr[4];
#pragma unroll
        for (int mi = 0; mi < 2; mi++)
            aaddr[mi] = smaddr(As + (wm + mi * 16 + a_row) * AST + a_kof);
#pragma unroll
        for (int p = 0; p < 4; p++)
            baddr[p] = smaddr(Ws + (wn + (2 * p + b_ni) * 8 + lrow) * AST + b_kof);

#pragma unroll
        for (int kk = 0; kk < 4; kk++) {
            const uint32_t kbB = kk * 32;     // 8 floats
            uint32_t a[2][4];
            ldsm_x4(a[0][0], a[0][1], a[0][2], a[0][3], aaddr[0] + kbB);
            ldsm_x4(a[1][0], a[1][1], a[1][2], a[1][3], aaddr[1] + kbB);
#pragma unroll
            for (int p = 0; p < 4; p++) {
                uint32_t b0, b1, b2, b3;
                ldsm_x4(b0, b1, b2, b3, baddr[p] + kbB);
                mma_tf32(c[0][2*p    ], a[0][0], a[0][1], a[0][2], a[0][3], b0, b1);
                mma_tf32(c[1][2*p    ], a[1][0], a[1][1], a[1][2], a[1][3], b0, b1);
                mma_tf32(c[0][2*p + 1], a[0][0], a[0][1], a[0][2], a[0][3], b2, b3);
                mma_tf32(c[1][2*p + 1], a[1][0], a[1][1], a[1][2], a[1][3], b2, b3);
            }
        }
        __syncthreads();
    }

    if (DO_QKV) {
        const int part = (int)blockIdx.x % 3;       // 0=q, 1=v, 2=k
        const int mp   = (int)blockIdx.x / 3;
        float* dst = (part == 0) ? g_q : (part == 1) ? g_v : g_k;
#pragma unroll
        for (int mi = 0; mi < 2; mi++) {
#pragma unroll
            for (int ni = 0; ni < 8; ni++) {
                int c_local = wn + ni * 8 + 2 * tig;    // even, in [0,128)
                int rhead = c_local >> 6;
                int d = c_local & 63;
                int h = mp * 2 + rhead;
                bool rope = (part != 1) && (d < RDdim);
                float inv = 0.0f;
                if (rope) {
                    int fi = d >> 1;
                    inv = exp2f(-(float)fi * 0.8304820237218405f); // 10000^(-2i/RD)
                }
#pragma unroll
                for (int half = 0; half < 2; half++) {
                    int row = m0 + wm + mi * 16 + gid + half * 8;
                    float v0 = c[mi][ni][half * 2];
                    float v1 = c[mi][ni][half * 2 + 1];
                    int b  = row >> 11;
                    int sl = row & 2047;
                    if (rope) {
                        float ang = (float)sl * inv;
                        float sn, cs;
                        sincosf(ang, &sn, &cs);
                        float e = v0 * cs - v1 * sn;
                        float o = v1 * cs + v0 * sn;
                        v0 = e; v1 = o;
                    }
                    float2 st = make_float2(to_tf32(v0), to_tf32(v1));
                    *(float2*)(dst + ((size_t)(b * Hdim + h) * Sdim + sl) * HDdim + d) = st;
                }
            }
        }
    } else {
#pragma unroll
        for (int mi = 0; mi < 2; mi++) {
#pragma unroll
            for (int ni = 0; ni < 8; ni++) {
                int r  = m0 + wm + mi * 16 + gid;
                int cc = n0 + wn + ni * 8 + 2 * tig;
                float2 v01 = make_float2(c[mi][ni][0], c[mi][ni][1]);
                float2 v23 = make_float2(c[mi][ni][2], c[mi][ni][3]);
                *(float2*)(C + (size_t)r * N + cc)       = v01;
                *(float2*)(C + (size_t)(r + 8) * N + cc) = v23;
            }
        }
    }
}

// ---------------------------------------------------------------------------
// Flash attention: 128-query x 128-key tiles, 8 warps, 2-stage cp.async,
// LDSM K-fragment loads, shuffle-transpose P, scalar LDS V loads.
// ---------------------------------------------------------------------------
#define KST 68
#define KTILE 128
#define TILE_F (KTILE * KST)
__global__ void __launch_bounds__(256) flash_mma()
{
    extern __shared__ float fsm[];
    const int qt  = 15 - (int)blockIdx.x;   // heavy tiles first
    const int bh  = blockIdx.y;
    const int tid = threadIdx.x;
    const int lane = tid & 31, w = tid >> 5;
    const int gid = lane >> 2, tig = lane & 3;
    const int lrow = lane & 7, lmat = lane >> 3;
    const int b_ni = lmat >> 1, b_kof = (lmat & 1) * 4;

    const float* Kh = g_k + (size_t)bh * Sdim * HDdim;
    const float* Vh = g_v + (size_t)bh * Sdim * HDdim;

    auto issueKV = [&](int kt, int st) {
        const float* Kb = Kh + (size_t)kt * KTILE * HDdim;
        const float* Vb = Vh + (size_t)kt * KTILE * HDdim;
        float* Ks = fsm + st * (2 * TILE_F);
        float* Vs = Ks + TILE_F;
#pragma unroll
        for (int it = 0; it < 8; it++) {
            int idx = tid + it * 256;          // 0..2047
            int r = idx >> 4, c4 = idx & 15;
            cp_async16(smaddr(Ks + r * KST + c4 * 4), Kb + (size_t)r * HDdim + c4 * 4);
            cp_async16(smaddr(Vs + r * KST + c4 * 4), Vb + (size_t)r * HDdim + c4 * 4);
        }
        cp_commit();
    };

    const int nk = qt + 1;
    issueKV(0, 0);

    // Q fragments straight from gmem (values already tf32-rounded)
    const float* Qb = g_q + ((size_t)bh * Sdim + qt * 128 + w * 16) * HDdim;
    uint32_t qa[8][4];
#pragma unroll
    for (int kk = 0; kk < 8; kk++) {
        qa[kk][0] = f2u(Qb[(size_t)(gid    ) * HDdim + kk * 8 + tig    ]);
        qa[kk][1] = f2u(Qb[(size_t)(gid + 8) * HDdim + kk * 8 + tig    ]);
        qa[kk][2] = f2u(Qb[(size_t)(gid    ) * HDdim + kk * 8 + tig + 4]);
        qa[kk][3] = f2u(Qb[(size_t)(gid + 8) * HDdim + kk * 8 + tig + 4]);
    }

    float m0r = -1e30f, m1r = -1e30f, l0 = 0.0f, l1 = 0.0f;
    float o[8][4];
#pragma unroll
    for (int ni = 0; ni < 8; ni++)
#pragma unroll
        for (int j = 0; j < 4; j++) o[ni][j] = 0.0f;

    const float scale = 0.125f;                 // 1/sqrt(64)
    const int row0 = qt * 128 + w * 16 + gid;   // thread's rows (row0, row0+8)

    for (int kt = 0; kt < nk; kt++) {
        if (kt + 1 < nk) { issueKV(kt + 1, (kt + 1) & 1); cp_wait<1>(); }
        else             { cp_wait<0>(); }
        __syncthreads();
        const float* Ks = fsm + (kt & 1) * (2 * TILE_F);
        const float* Vs = Ks + TILE_F;

        // ldmatrix base addresses for K (8 ni-pairs cover 128 keys)
        uint32_t kaddr[8];
#pragma unroll
        for (int p = 0; p < 8; p++)
            kaddr[p] = smaddr(Ks + ((2 * p + b_ni) * 8 + lrow) * KST + b_kof);

        // S = Q @ K^T  (16 rows x 128 keys per warp)
        float s[16][4];
#pragma unroll
        for (int ni = 0; ni < 16; ni++)
#pragma unroll
            for (int j = 0; j < 4; j++) s[ni][j] = 0.0f;
#pragma unroll
        for (int kk = 0; kk < 8; kk++) {
            const uint32_t kbB = kk * 32;
#pragma unroll
            for (int p = 0; p < 8; p++) {
                uint32_t b0, b1, b2, b3;
                ldsm_x4(b0, b1, b2, b3, kaddr[p] + kbB);
                mma_tf32(s[2*p    ], qa[kk][0], qa[kk][1], qa[kk][2], qa[kk][3], b0, b1);
                mma_tf32(s[2*p + 1], qa[kk][0], qa[kk][1], qa[kk][2], qa[kk][3], b2, b3);
            }
        }

        // scale + causal mask (only the diagonal tile is partial)
        if (kt == qt) {
#pragma unroll
            for (int ni = 0; ni < 16; ni++)
#pragma unroll
                for (int j = 0; j < 4; j++) {
                    int col  = kt * KTILE + ni * 8 + 2 * tig + (j & 1);
                    int rowg = row0 + ((j >= 2) ? 8 : 0);
                    s[ni][j] = (col > rowg) ? -1e9f : s[ni][j] * scale;
                }
        } else {
#pragma unroll
            for (int ni = 0; ni < 16; ni++)
#pragma unroll
                for (int j = 0; j < 4; j++) s[ni][j] *= scale;
        }

        // online softmax (rows gid, gid+8)
        float mx0 = -1e30f, mx1 = -1e30f;
#pragma unroll
        for (int ni = 0; ni < 16; ni++) {
            mx0 = fmaxf(mx0, fmaxf(s[ni][0], s[ni][1]));
            mx1 = fmaxf(mx1, fmaxf(s[ni][2], s[ni][3]));
        }
        mx0 = fmaxf(mx0, __shfl_xor_sync(FULLMASK, mx0, 1));
        mx0 = fmaxf(mx0, __shfl_xor_sync(FULLMASK, mx0, 2));
        mx1 = fmaxf(mx1, __shfl_xor_sync(FULLMASK, mx1, 1));
        mx1 = fmaxf(mx1, __shfl_xor_sync(FULLMASK, mx1, 2));

        float mn0 = fmaxf(m0r, mx0), mn1 = fmaxf(m1r, mx1);
        float al0 = __expf(m0r - mn0), al1 = __expf(m1r - mn1);
        float rs0 = 0.0f, rs1 = 0.0f;
#pragma unroll
        for (int ni = 0; ni < 16; ni++) {
            float p0 = __expf(s[ni][0] - mn0); s[ni][0] = p0; rs0 += p0;
            float p1 = __expf(s[ni][1] - mn0); s[ni][1] = p1; rs0 += p1;
            float p2 = __expf(s[ni][2] - mn1); s[ni][2] = p2; rs1 += p2;
            float p3 = __expf(s[ni][3] - mn1); s[ni][3] = p3; rs1 += p3;
        }
        rs0 += __shfl_xor_sync(FULLMASK, rs0, 1);
        rs0 += __shfl_xor_sync(FULLMASK, rs0, 2);
        rs1 += __shfl_xor_sync(FULLMASK, rs1, 1);
        rs1 += __shfl_xor_sync(FULLMASK, rs1, 2);

        l0 = l0 * al0 + rs0;  l1 = l1 * al1 + rs1;
        m0r = mn0;  m1r = mn1;
#pragma unroll
        for (int ni = 0; ni < 8; ni++) {
            o[ni][0] *= al0; o[ni][1] *= al0;
            o[ni][2] *= al1; o[ni][3] *= al1;
        }

        // O += P @ V : C-frag -> A-frag via register shuffles (16 k-chunks)
        const int src0 = (lane & 28) | (tig >> 1);
        const int src1 = src0 + 2;
        const bool odd = (tig & 1);
#pragma unroll
        for (int kk = 0; kk < 16; kk++) {
            float v00 = __shfl_sync(FULLMASK, s[kk][0], src0);
            float v01 = __shfl_sync(FULLMASK, s[kk][1], src0);
            float v10 = __shfl_sync(FULLMASK, s[kk][2], src0);
            float v11 = __shfl_sync(FULLMASK, s[kk][3], src0);
            float u00 = __shfl_sync(FULLMASK, s[kk][0], src1);
            float u01 = __shfl_sync(FULLMASK, s[kk][1], src1);
            float u10 = __shfl_sync(FULLMASK, s[kk][2], src1);
            float u11 = __shfl_sync(FULLMASK, s[kk][3], src1);
            uint32_t pa0 = f2u(to_tf32(odd ? v01 : v00));
            uint32_t pa1 = f2u(to_tf32(odd ? v11 : v10));
            uint32_t pa2 = f2u(to_tf32(odd ? u01 : u00));
            uint32_t pa3 = f2u(to_tf32(odd ? u11 : u10));
            int kb = kk * 8;
#pragma unroll
            for (int ni = 0; ni < 8; ni++) {
                uint32_t b0 = f2u(Vs[(kb + tig    ) * KST + ni * 8 + gid]);
                uint32_t b1 = f2u(Vs[(kb + tig + 4) * KST + ni * 8 + gid]);
                mma_tf32(o[ni], pa0, pa1, pa2, pa3, b0, b1);
            }
        }
        __syncthreads();
    }

    // epilogue -> g_ctx[b, s, h, d] (tf32-rounded for the out-proj GEMM)
    const int b = bh >> 4, h = bh & 15;
    const float inv0 = 1.0f / l0, inv1 = 1.0f / l1;
#pragma unroll
    for (int ni = 0; ni < 8; ni++) {
        int d0 = ni * 8 + 2 * tig;
        float2 v01 = make_float2(to_tf32(o[ni][0] * inv0), to_tf32(o[ni][1] * inv0));
        float2 v23 = make_float2(to_tf32(o[ni][2] * inv1), to_tf32(o[ni][3] * inv1));
        *(float2*)(g_ctx + (size_t)((b * Sdim + row0    ) * Hdim + h) * HDdim + d0) = v01;
        *(float2*)(g_ctx + (size_t)((b * Sdim + row0 + 8) * Hdim + h) * HDdim + d0) = v23;
    }
}

// ---------------------------------------------------------------------------
extern "C" void kernel_launch(void* const* d_in, const int* in_sizes, int n_in,
                              void* d_out, int out_size)
{
    const float* hs    = (const float*)d_in[0];   // [B,S,E]
    const float* w_qkv = (const float*)d_in[1];   // [3E,E]
    const float* w_out = (const float*)d_in[2];   // [E,E]
    float* out = (float*)d_out;                   // [B,S,E]

    float *p_ctx, *p_hs, *p_wqkv, *p_wout;
    cudaGetSymbolAddress((void**)&p_ctx,  g_ctx);
    cudaGetSymbolAddress((void**)&p_hs,   g_hs_r);
    cudaGetSymbolAddress((void**)&p_wqkv, g_wqkv_r);
    cudaGetSymbolAddress((void**)&p_wout, g_wout_r);

    const int GS = 4 * 128 * AST * sizeof(float);   // 73728 B (2 stages A+W)
    const int FS = 4 * TILE_F * sizeof(float);      // 139264 B (2 stages K+V)
    cudaFuncSetAttribute(sgemm_tf32<1>, cudaFuncAttributeMaxDynamicSharedMemorySize, GS);
    cudaFuncSetAttribute(sgemm_tf32<0>, cudaFuncAttributeMaxDynamicSharedMemorySize, GS);
    cudaFuncSetAttribute(flash_mma,     cudaFuncAttributeMaxDynamicSharedMemorySize, FS);

    // 0) pre-round inputs to tf32
    {
        int n4;
        n4 = MROWS * Edim / 4;
        round_tf32<<<(n4 + 255) / 256, 256>>>(hs, p_hs, n4);
        n4 = 3 * Edim * Edim / 4;
        round_tf32<<<(n4 + 255) / 256, 256>>>(w_qkv, p_wqkv, n4);
        n4 = Edim * Edim / 4;
        round_tf32<<<(n4 + 255) / 256, 256>>>(w_out, p_wout, n4);
    }
    // 1) QKV projection with FUSED split + RoPE epilogue -> g_q/g_k/g_v
    {
        dim3 grid(3 * Edim / 128, MROWS / 128);
        sgemm_tf32<1><<<grid, 256, GS>>>(p_hs, p_wqkv, nullptr, MROWS, 3 * Edim, Edim);
    }
    // 2) flash attention (128-query x 128-key tiles, LDSM K loads)
    {
        dim3 grid(Sdim / 128, Bdim * Hdim);
        flash_mma<<<grid, 256, FS>>>();
    }
    // 3) output projection: [4096,1024] @ [1024,1024]^T
    {
        dim3 grid(Edim / 128, MROWS / 128);
        sgemm_tf32<0><<<grid, 256, GS>>>(p_ctx, p_wout, out, MROWS, Edim, Edim);
    }
}

// round 10
// speedup vs baseline: 1.2590x; 1.0554x over previous
#include <cuda_runtime.h>
#include <math.h>
#include <stdint.h>

#define Bdim 2
#define Sdim 2048
#define Edim 1024
#define Hdim 16
#define HDdim 64
#define RDdim 32
#define MROWS (Bdim*Sdim)  // 4096
#define FULLMASK 0xffffffffu

// Scratch (allocation-free per harness rules)
__device__ float g_q[Bdim*Hdim*Sdim*HDdim];   // tf32-pre-rounded, [b,h,s,d]
__device__ float g_k[Bdim*Hdim*Sdim*HDdim];   // [b,h,s,d]
__device__ float g_vt[Bdim*Hdim*HDdim*Sdim];  // [b,h,d,s]  (transposed V!)
__device__ float g_ctx[Bdim*Sdim*Edim];       // [b,s,h,d], tf32-pre-rounded
__device__ float g_hs_r[MROWS*Edim];          // hs rounded to tf32
__device__ float g_wqkv_r[3*Edim*Edim];       // w_qkv rounded
__device__ float g_wout_r[Edim*Edim];         // w_out rounded

__device__ __forceinline__ float to_tf32(float x) {
    uint32_t u;
    asm("cvt.rna.tf32.f32 %0, %1;" : "=r"(u) : "f"(x));
    return __uint_as_float(u);
}
__device__ __forceinline__ uint32_t f2u(float x) { return __float_as_uint(x); }
__device__ __forceinline__ uint32_t smaddr(const void* p) {
    return (uint32_t)__cvta_generic_to_shared(p);
}
__device__ __forceinline__ void cp_async16(uint32_t dst, const void* src) {
    asm volatile("cp.async.cg.shared.global [%0], [%1], 16;" :: "r"(dst), "l"(src));
}
__device__ __forceinline__ void cp_commit() {
    asm volatile("cp.async.commit_group;");
}
template<int N> __device__ __forceinline__ void cp_wait() {
    asm volatile("cp.async.wait_group %0;" :: "n"(N));
}

__device__ __forceinline__ void ldsm_x4(uint32_t& r0, uint32_t& r1,
                                        uint32_t& r2, uint32_t& r3, uint32_t addr)
{
    asm volatile("ldmatrix.sync.aligned.m8n8.x4.shared.b16 {%0,%1,%2,%3}, [%4];"
        : "=r"(r0), "=r"(r1), "=r"(r2), "=r"(r3) : "r"(addr));
}

__device__ __forceinline__ void mma_tf32(float c[4],
    uint32_t a0, uint32_t a1, uint32_t a2, uint32_t a3,
    uint32_t b0, uint32_t b1)
{
    asm volatile(
        "mma.sync.aligned.m16n8k8.row.col.f32.tf32.tf32.f32 "
        "{%0,%1,%2,%3}, {%4,%5,%6,%7}, {%8,%9}, {%0,%1,%2,%3};"
        : "+f"(c[0]), "+f"(c[1]), "+f"(c[2]), "+f"(c[3])
        : "r"(a0), "r"(a1), "r"(a2), "r"(a3), "r"(b0), "r"(b1));
}

// ---------------------------------------------------------------------------
// Pre-round to tf32
// ---------------------------------------------------------------------------
__global__ __launch_bounds__(256) void round_tf32(
    const float* __restrict__ src, float* __restrict__ dst, int n4)
{
    int i = blockIdx.x * blockDim.x + threadIdx.x;
    if (i >= n4) return;
    float4 v = ((const float4*)src)[i];
    v.x = to_tf32(v.x); v.y = to_tf32(v.y);
    v.z = to_tf32(v.z); v.w = to_tf32(v.w);
    ((float4*)dst)[i] = v;
}

// ---------------------------------------------------------------------------
// TF32 GEMM, 3-stage cp.async ring, single __syncthreads/iter, LDSM frags.
// BM=128, BN=128, BK=32, 256 threads (8 warps 4x2), warp tile 32x64.
// DO_QKV=1: fused split + RoPE epilogue (part = blockIdx.x % 3: 0=q,1=v,2=k);
//           V is stored TRANSPOSED into g_vt[b,h,d,s].
// ---------------------------------------------------------------------------
#define AST 36
#define GSTAGE_F (2 * 128 * AST)
template<int DO_QKV>
__global__ __launch_bounds__(256) void sgemm_tf32(
    const float* __restrict__ A, const float* __restrict__ W,
    float* __restrict__ C, int M, int N, int K)
{
    extern __shared__ float sm[];    // 3 stages x [A(128*AST) | W(128*AST)]
    const int tid  = threadIdx.x;
    const int lane = tid & 31, wid = tid >> 5;
    const int gid  = lane >> 2, tig = lane & 3;
    const int wm   = (wid & 3) * 32;
    const int wn   = (wid >> 2) * 64;
    const int m0   = blockIdx.y * 128;
    const int n0   = blockIdx.x * 128;

    const int lrow = lane & 7, lmat = lane >> 3;
    const int a_row = (lmat & 1) * 8 + lrow;
    const int a_kof = (lmat >> 1) * 4;
    const int b_ni  = lmat >> 1;
    const int b_kof = (lmat & 1) * 4;

    auto issue = [&](int t) {
        float* As = sm + (t % 3) * GSTAGE_F;
        float* Ws = As + 128 * AST;
        const int k0 = t * 32;
#pragma unroll
        for (int it = 0; it < 4; it++) {
            int idx = tid + it * 256;
            int r = idx >> 3, c4 = idx & 7;
            cp_async16(smaddr(As + r * AST + c4 * 4), A + (size_t)(m0 + r) * K + k0 + c4 * 4);
            cp_async16(smaddr(Ws + r * AST + c4 * 4), W + (size_t)(n0 + r) * K + k0 + c4 * 4);
        }
        cp_commit();
    };

    float c[2][8][4];
#pragma unroll
    for (int mi = 0; mi < 2; mi++)
#pragma unroll
        for (int ni = 0; ni < 8; ni++)
#pragma unroll
            for (int j = 0; j < 4; j++) c[mi][ni][j] = 0.0f;

    const int nt = K / 32;
    issue(0);
    issue(1);
    for (int t = 0; t < nt; t++) {
        if (t + 1 < nt) cp_wait<1>();
        else            cp_wait<0>();
        __syncthreads();                 // stage t visible; stage t-1 reads done
        if (t + 2 < nt) issue(t + 2);    // overwrites stage t-1: safe after sync

        const float* As = sm + (t % 3) * GSTAGE_F;
        const float* Ws = As + 128 * AST;
        uint32_t aaddr[2], baddr[4];
#pragma unroll
        for (int mi = 0; mi < 2; mi++)
            aaddr[mi] = smaddr(As + (wm + mi * 16 + a_row) * AST + a_kof);
#pragma unroll
        for (int p = 0; p < 4; p++)
            baddr[p] = smaddr(Ws + (wn + (2 * p + b_ni) * 8 + lrow) * AST + b_kof);

#pragma unroll
        for (int kk = 0; kk < 4; kk++) {
            const uint32_t kbB = kk * 32;
            uint32_t a[2][4];
            ldsm_x4(a[0][0], a[0][1], a[0][2], a[0][3], aaddr[0] + kbB);
            ldsm_x4(a[1][0], a[1][1], a[1][2], a[1][3], aaddr[1] + kbB);
#pragma unroll
            for (int p = 0; p < 4; p++) {
                uint32_t b0, b1, b2, b3;
                ldsm_x4(b0, b1, b2, b3, baddr[p] + kbB);
                mma_tf32(c[0][2*p    ], a[0][0], a[0][1], a[0][2], a[0][3], b0, b1);
                mma_tf32(c[1][2*p    ], a[1][0], a[1][1], a[1][2], a[1][3], b0, b1);
                mma_tf32(c[0][2*p + 1], a[0][0], a[0][1], a[0][2], a[0][3], b2, b3);
                mma_tf32(c[1][2*p + 1], a[1][0], a[1][1], a[1][2], a[1][3], b2, b3);
            }
        }
    }

    if (DO_QKV) {
        const int part = (int)blockIdx.x % 3;       // 0=q, 1=v, 2=k
        const int mp   = (int)blockIdx.x / 3;
        if (part == 1) {
            // V: store TRANSPOSED to g_vt[b,h,d,s]
#pragma unroll
            for (int mi = 0; mi < 2; mi++) {
#pragma unroll
                for (int ni = 0; ni < 8; ni++) {
                    int c_local = wn + ni * 8 + 2 * tig;
                    int rhead = c_local >> 6;
                    int d = c_local & 63;
                    int h = mp * 2 + rhead;
                    size_t base = (size_t)(0 * Hdim + h) * HDdim;  // b added below
#pragma unroll
                    for (int half = 0; half < 2; half++) {
                        int row = m0 + wm + mi * 16 + gid + half * 8;
                        int b  = row >> 11;
                        int sl = row & 2047;
                        size_t bb = ((size_t)(b * Hdim + h) * HDdim);
                        g_vt[(bb + d    ) * Sdim + sl] = to_tf32(c[mi][ni][half * 2    ]);
                        g_vt[(bb + d + 1) * Sdim + sl] = to_tf32(c[mi][ni][half * 2 + 1]);
                    }
                    (void)base;
                }
            }
        } else {
            float* dst = (part == 0) ? g_q : g_k;
#pragma unroll
            for (int mi = 0; mi < 2; mi++) {
#pragma unroll
                for (int ni = 0; ni < 8; ni++) {
                    int c_local = wn + ni * 8 + 2 * tig;
                    int rhead = c_local >> 6;
                    int d = c_local & 63;
                    int h = mp * 2 + rhead;
                    bool rope = (d < RDdim);
                    float inv = 0.0f;
                    if (rope) {
                        int fi = d >> 1;
                        inv = exp2f(-(float)fi * 0.8304820237218405f); // 10000^(-2i/RD)
                    }
#pragma unroll
                    for (int half = 0; half < 2; half++) {
                        int row = m0 + wm + mi * 16 + gid + half * 8;
                        float v0 = c[mi][ni][half * 2];
                        float v1 = c[mi][ni][half * 2 + 1];
                        int b  = row >> 11;
                        int sl = row & 2047;
                        if (rope) {
                            float ang = (float)sl * inv;
                            float sn, cs;
                            sincosf(ang, &sn, &cs);
                            float e = v0 * cs - v1 * sn;
                            float o = v1 * cs + v0 * sn;
                            v0 = e; v1 = o;
                        }
                        float2 st = make_float2(to_tf32(v0), to_tf32(v1));
                        *(float2*)(dst + ((size_t)(b * Hdim + h) * Sdim + sl) * HDdim + d) = st;
                    }
                }
            }
        }
    } else {
#pragma unroll
        for (int mi = 0; mi < 2; mi++) {
#pragma unroll
            for (int ni = 0; ni < 8; ni++) {
                int r  = m0 + wm + mi * 16 + gid;
                int cc = n0 + wn + ni * 8 + 2 * tig;
                float2 v01 = make_float2(c[mi][ni][0], c[mi][ni][1]);
                float2 v23 = make_float2(c[mi][ni][2], c[mi][ni][3]);
                *(float2*)(C + (size_t)r * N + cc)       = v01;
                *(float2*)(C + (size_t)(r + 8) * N + cc) = v23;
            }
        }
    }
}

// ---------------------------------------------------------------------------
// Flash attention: 128-query x 128-key tiles, 8 warps, 3-stage cp.async ring
// (single sync/iter), LDSM for BOTH K and V^T fragments.
// Stage = Ks[128][68] + Vt[64][132].
// ---------------------------------------------------------------------------
#define KST 68
#define VST 132
#define KTILE 128
#define FSTAGE_F (KTILE * KST + HDdim * VST)    // 17152 floats
__global__ void __launch_bounds__(256) flash_mma()
{
    extern __shared__ float fsm[];
    const int qt  = 15 - (int)blockIdx.x;   // heavy tiles first
    const int bh  = blockIdx.y;
    const int tid = threadIdx.x;
    const int lane = tid & 31, w = tid >> 5;
    const int gid = lane >> 2, tig = lane & 3;
    const int lrow = lane & 7, lmat = lane >> 3;
    const int b_ni = lmat >> 1, b_kof = (lmat & 1) * 4;

    const float* Kh  = g_k  + (size_t)bh * Sdim * HDdim;
    const float* Vtg = g_vt + (size_t)bh * HDdim * Sdim;

    auto issueKV = [&](int kt) {
        const float* Kb = Kh + (size_t)kt * KTILE * HDdim;
        float* Ks = fsm + (kt % 3) * FSTAGE_F;
        float* Vt = Ks + KTILE * KST;
#pragma unroll
        for (int it = 0; it < 8; it++) {       // K: 2048 16B chunks
            int idx = tid + it * 256;
            int r = idx >> 4, c4 = idx & 15;
            cp_async16(smaddr(Ks + r * KST + c4 * 4), Kb + (size_t)r * HDdim + c4 * 4);
        }
#pragma unroll
        for (int it = 0; it < 8; it++) {       // Vt: 64 rows x 32 chunks
            int idx = tid + it * 256;
            int r = idx >> 5, c4 = idx & 31;
            cp_async16(smaddr(Vt + r * VST + c4 * 4),
                       Vtg + (size_t)r * Sdim + kt * KTILE + c4 * 4);
        }
        cp_commit();
    };

    const int nk = qt + 1;
    issueKV(0);
    if (nk > 1) issueKV(1);

    // Q fragments straight from gmem (values already tf32-rounded)
    const float* Qb = g_q + ((size_t)bh * Sdim + qt * 128 + w * 16) * HDdim;
    uint32_t qa[8][4];
#pragma unroll
    for (int kk = 0; kk < 8; kk++) {
        qa[kk][0] = f2u(Qb[(size_t)(gid    ) * HDdim + kk * 8 + tig    ]);
        qa[kk][1] = f2u(Qb[(size_t)(gid + 8) * HDdim + kk * 8 + tig    ]);
        qa[kk][2] = f2u(Qb[(size_t)(gid    ) * HDdim + kk * 8 + tig + 4]);
        qa[kk][3] = f2u(Qb[(size_t)(gid + 8) * HDdim + kk * 8 + tig + 4]);
    }

    float m0r = -1e30f, m1r = -1e30f, l0 = 0.0f, l1 = 0.0f;
    float o[8][4];
#pragma unroll
    for (int ni = 0; ni < 8; ni++)
#pragma unroll
        for (int j = 0; j < 4; j++) o[ni][j] = 0.0f;

    const float scale = 0.125f;                 // 1/sqrt(64)
    const int row0 = qt * 128 + w * 16 + gid;

    for (int kt = 0; kt < nk; kt++) {
        if (kt + 1 < nk) cp_wait<1>();
        else             cp_wait<0>();
        __syncthreads();
        if (kt + 2 < nk) issueKV(kt + 2);

        const float* Ks = fsm + (kt % 3) * FSTAGE_F;
        const float* Vt = Ks + KTILE * KST;

        uint32_t kaddr[8];
#pragma unroll
        for (int p = 0; p < 8; p++)
            kaddr[p] = smaddr(Ks + ((2 * p + b_ni) * 8 + lrow) * KST + b_kof);

        // S = Q @ K^T
        float s[16][4];
#pragma unroll
        for (int ni = 0; ni < 16; ni++)
#pragma unroll
            for (int j = 0; j < 4; j++) s[ni][j] = 0.0f;
#pragma unroll
        for (int kk = 0; kk < 8; kk++) {
            const uint32_t kbB = kk * 32;
#pragma unroll
            for (int p = 0; p < 8; p++) {
                uint32_t b0, b1, b2, b3;
                ldsm_x4(b0, b1, b2, b3, kaddr[p] + kbB);
                mma_tf32(s[2*p    ], qa[kk][0], qa[kk][1], qa[kk][2], qa[kk][3], b0, b1);
                mma_tf32(s[2*p + 1], qa[kk][0], qa[kk][1], qa[kk][2], qa[kk][3], b2, b3);
            }
        }

        // scale + causal mask (only diagonal tile partial)
        if (kt == qt) {
#pragma unroll
            for (int ni = 0; ni < 16; ni++)
#pragma unroll
                for (int j = 0; j < 4; j++) {
                    int col  = kt * KTILE + ni * 8 + 2 * tig + (j & 1);
                    int rowg = row0 + ((j >= 2) ? 8 : 0);
                    s[ni][j] = (col > rowg) ? -1e9f : s[ni][j] * scale;
                }
        } else {
#pragma unroll
            for (int ni = 0; ni < 16; ni++)
#pragma unroll
                for (int j = 0; j < 4; j++) s[ni][j] *= scale;
        }

        // online softmax
        float mx0 = -1e30f, mx1 = -1e30f;
#pragma unroll
        for (int ni = 0; ni < 16; ni++) {
            mx0 = fmaxf(mx0, fmaxf(s[ni][0], s[ni][1]));
            mx1 = fmaxf(mx1, fmaxf(s[ni][2], s[ni][3]));
        }
        mx0 = fmaxf(mx0, __shfl_xor_sync(FULLMASK, mx0, 1));
        mx0 = fmaxf(mx0, __shfl_xor_sync(FULLMASK, mx0, 2));
        mx1 = fmaxf(mx1, __shfl_xor_sync(FULLMASK, mx1, 1));
        mx1 = fmaxf(mx1, __shfl_xor_sync(FULLMASK, mx1, 2));

        float mn0 = fmaxf(m0r, mx0), mn1 = fmaxf(m1r, mx1);
        float al0 = __expf(m0r - mn0), al1 = __expf(m1r - mn1);
        float rs0 = 0.0f, rs1 = 0.0f;
#pragma unroll
        for (int ni = 0; ni < 16; ni++) {
            float p0 = __expf(s[ni][0] - mn0); s[ni][0] = p0; rs0 += p0;
            float p1 = __expf(s[ni][1] - mn0); s[ni][1] = p1; rs0 += p1;
            float p2 = __expf(s[ni][2] - mn1); s[ni][2] = p2; rs1 += p2;
            float p3 = __expf(s[ni][3] - mn1); s[ni][3] = p3; rs1 += p3;
        }
        rs0 += __shfl_xor_sync(FULLMASK, rs0, 1);
        rs0 += __shfl_xor_sync(FULLMASK, rs0, 2);
        rs1 += __shfl_xor_sync(FULLMASK, rs1, 1);
        rs1 += __shfl_xor_sync(FULLMASK, rs1, 2);

        l0 = l0 * al0 + rs0;  l1 = l1 * al1 + rs1;
        m0r = mn0;  m1r = mn1;
#pragma unroll
        for (int ni = 0; ni < 8; ni++) {
            o[ni][0] *= al0; o[ni][1] *= al0;
            o[ni][2] *= al1; o[ni][3] *= al1;
        }

        // O += P @ V : A-frag via shuffle transpose, B-frag via LDSM on Vt
        uint32_t vaddr[4];
#pragma unroll
        for (int p = 0; p < 4; p++)
            vaddr[p] = smaddr(Vt + ((2 * p + b_ni) * 8 + lrow) * VST + b_kof);

        const int src0 = (lane & 28) | (tig >> 1);
        const int src1 = src0 + 2;
        const bool odd = (tig & 1);
#pragma unroll
        for (int kk = 0; kk < 16; kk++) {
            float v00 = __shfl_sync(FULLMASK, s[kk][0], src0);
            float v01 = __shfl_sync(FULLMASK, s[kk][1], src0);
            float v10 = __shfl_sync(FULLMASK, s[kk][2], src0);
            float v11 = __shfl_sync(FULLMASK, s[kk][3], src0);
            float u00 = __shfl_sync(FULLMASK, s[kk][0], src1);
            float u01 = __shfl_sync(FULLMASK, s[kk][1], src1);
            float u10 = __shfl_sync(FULLMASK, s[kk][2], src1);
            float u11 = __shfl_sync(FULLMASK, s[kk][3], src1);
            uint32_t pa0 = f2u(to_tf32(odd ? v01 : v00));
            uint32_t pa1 = f2u(to_tf32(odd ? v11 : v10));
            uint32_t pa2 = f2u(to_tf32(odd ? u01 : u00));
            uint32_t pa3 = f2u(to_tf32(odd ? u11 : u10));
            const uint32_t kbB = kk * 32;     // key offset in bytes
#pragma unroll
            for (int p = 0; p < 4; p++) {
                uint32_t b0, b1, b2, b3;
                ldsm_x4(b0, b1, b2, b3, vaddr[p] + kbB);
                mma_tf32(o[2*p    ], pa0, pa1, pa2, pa3, b0, b1);
                mma_tf32(o[2*p + 1], pa0, pa1, pa2, pa3, b2, b3);
            }
        }
    }

    // epilogue -> g_ctx[b, s, h, d] (tf32-rounded for the out-proj GEMM)
    const int b = bh >> 4, h = bh & 15;
    const float inv0 = 1.0f / l0, inv1 = 1.0f / l1;
#pragma unroll
    for (int ni = 0; ni < 8; ni++) {
        int d0 = ni * 8 + 2 * tig;
        float2 v01 = make_float2(to_tf32(o[ni][0] * inv0), to_tf32(o[ni][1] * inv0));
        float2 v23 = make_float2(to_tf32(o[ni][2] * inv1), to_tf32(o[ni][3] * inv1));
        *(float2*)(g_ctx + (size_t)((b * Sdim + row0    ) * Hdim + h) * HDdim + d0) = v01;
        *(float2*)(g_ctx + (size_t)((b * Sdim + row0 + 8) * Hdim + h) * HDdim + d0) = v23;
    }
}

// ---------------------------------------------------------------------------
extern "C" void kernel_launch(void* const* d_in, const int* in_sizes, int n_in,
                              void* d_out, int out_size)
{
    const float* hs    = (const float*)d_in[0];   // [B,S,E]
    const float* w_qkv = (const float*)d_in[1];   // [3E,E]
    const float* w_out = (const float*)d_in[2];   // [E,E]
    float* out = (float*)d_out;                   // [B,S,E]

    float *p_ctx, *p_hs, *p_wqkv, *p_wout;
    cudaGetSymbolAddress((void**)&p_ctx,  g_ctx);
    cudaGetSymbolAddress((void**)&p_hs,   g_hs_r);
    cudaGetSymbolAddress((void**)&p_wqkv, g_wqkv_r);
    cudaGetSymbolAddress((void**)&p_wout, g_wout_r);

    const int GS = 3 * GSTAGE_F * sizeof(float);    // 110592 B (3 stages A+W)
    const int FS = 3 * FSTAGE_F * sizeof(float);    // 205824 B (3 stages K+Vt)
    cudaFuncSetAttribute(sgemm_tf32<1>, cudaFuncAttributeMaxDynamicSharedMemorySize, GS);
    cudaFuncSetAttribute(sgemm_tf32<0>, cudaFuncAttributeMaxDynamicSharedMemorySize, GS);
    cudaFuncSetAttribute(flash_mma,     cudaFuncAttributeMaxDynamicSharedMemorySize, FS);
    cudaFuncSetAttribute(sgemm_tf32<1>, cudaFuncAttributePreferredSharedMemoryCarveout, 100);
    cudaFuncSetAttribute(sgemm_tf32<0>, cudaFuncAttributePreferredSharedMemoryCarveout, 100);
    cudaFuncSetAttribute(flash_mma,     cudaFuncAttributePreferredSharedMemoryCarveout, 100);

    // 0) pre-round inputs to tf32
    {
        int n4;
        n4 = MROWS * Edim / 4;
        round_tf32<<<(n4 + 255) / 256, 256>>>(hs, p_hs, n4);
        n4 = 3 * Edim * Edim / 4;
        round_tf32<<<(n4 + 255) / 256, 256>>>(w_qkv, p_wqkv, n4);
        n4 = Edim * Edim / 4;
        round_tf32<<<(n4 + 255) / 256, 256>>>(w_out, p_wout, n4);
    }
    // 1) QKV projection with FUSED split + RoPE epilogue -> g_q/g_k/g_vt
    {
        dim3 grid(3 * Edim / 128, MROWS / 128);
        sgemm_tf32<1><<<grid, 256, GS>>>(p_hs, p_wqkv, nullptr, MROWS, 3 * Edim, Edim);
    }
    // 2) flash attention (128x128 tiles, LDSM K and V^T loads)
    {
        dim3 grid(Sdim / 128, Bdim * Hdim);
        flash_mma<<<grid, 256, FS>>>();
    }
    // 3) output projection: [4096,1024] @ [1024,1024]^T
    {
        dim3 grid(Edim / 128, MROWS / 128);
        sgemm_tf32<0><<<grid, 256, GS>>>(p_ctx, p_wout, out, MROWS, Edim, Edim);
    }
}